// round 1
// baseline (speedup 1.0000x reference)
#include <cuda_runtime.h>

// Implicit-GEMM direct conv: out[n,oc,oh,ow] = sum_{c,r,s} x[n,c,oh+r-1,ow+s-1] * w[oc,c,r,s] + bias[oc]
// GEMM view: M=256 (oc), N=100352 (n*56*56 pixels), K=1152 (c*9+r*3+s)
// Tiles: BM=128, BN=128, BK=16, 256 threads, 8x8 per thread (4 quadrants of 4x4).

#define C_IN   128
#define HW_IMG (56 * 56)     // 3136
#define KDIM   (C_IN * 9)    // 1152
#define BM 128
#define BN 128
#define BK 16
#define SPAD 4

__global__ __launch_bounds__(256, 2)
void conv_igemm_kernel(const float* __restrict__ x,
                       const float* __restrict__ w,
                       const float* __restrict__ bias,
                       float* __restrict__ out)
{
    __shared__ float As[BK][BM + SPAD];   // [k][oc]
    __shared__ float Bs[BK][BN + SPAD];   // [k][pix]

    const int tid = threadIdx.x;
    const int tx  = tid & 15;             // 0..15
    const int ty  = tid >> 4;             // 0..15

    const int pix0 = blockIdx.x * BN;     // global pixel base (n*3136 + oh*56 + ow)
    const int oc0  = blockIdx.y * BM;     // output-channel base

    // ---- B-load role: this thread fills pixel column pixL for 8 k-rows ----
    const int pixL = tid & 127;           // local pixel column
    const int kb   = tid >> 7;            // 0/1: k-row parity
    const int pixg = pix0 + pixL;
    const int n_b  = pixg / HW_IMG;
    const int hw_b = pixg % HW_IMG;
    const int oh   = hw_b / 56;
    const int ow   = hw_b % 56;
    const float* __restrict__ xn = x + (long long)n_b * C_IN * HW_IMG;

    float acc[8][8];
    #pragma unroll
    for (int i = 0; i < 8; i++)
        #pragma unroll
        for (int j = 0; j < 8; j++)
            acc[i][j] = 0.0f;

    for (int k0 = 0; k0 < KDIM; k0 += BK) {
        // ---- load A tile: weights [128 oc x 16 k], contiguous float4 along k ----
        #pragma unroll
        for (int i = 0; i < 2; i++) {
            const int f   = tid + i * 256;        // 0..511
            const int oc  = f >> 2;               // 0..127
            const int k4  = f & 3;                // which float4 along k
            const float4 v = *(const float4*)(w + (long long)(oc0 + oc) * KDIM + k0 + k4 * 4);
            As[k4 * 4 + 0][oc] = v.x;
            As[k4 * 4 + 1][oc] = v.y;
            As[k4 * 4 + 2][oc] = v.z;
            As[k4 * 4 + 3][oc] = v.w;
        }
        // ---- load B tile: im2col gather, 8 k-rows per thread, fixed pixel ----
        #pragma unroll
        for (int e = 0; e < 8; e++) {
            const int k  = e * 2 + kb;            // 0..15
            const int kk = k0 + k;
            const int c  = kk / 9;
            const int rs = kk - c * 9;
            const int r  = rs / 3;
            const int s  = rs - r * 3;
            const int ih = oh + r - 1;
            const int iw = ow + s - 1;
            float v = 0.0f;
            if ((unsigned)ih < 56u && (unsigned)iw < 56u)
                v = xn[(c * 56 + ih) * 56 + iw];
            Bs[k][pixL] = v;
        }
        __syncthreads();

        // ---- 128x128x16 MAC ----
        #pragma unroll
        for (int k = 0; k < BK; k++) {
            const float4 a0 = *(const float4*)&As[k][ty * 4];
            const float4 a1 = *(const float4*)&As[k][64 + ty * 4];
            const float4 b0 = *(const float4*)&Bs[k][tx * 4];
            const float4 b1 = *(const float4*)&Bs[k][64 + tx * 4];
            const float a[8] = {a0.x, a0.y, a0.z, a0.w, a1.x, a1.y, a1.z, a1.w};
            const float b[8] = {b0.x, b0.y, b0.z, b0.w, b1.x, b1.y, b1.z, b1.w};
            #pragma unroll
            for (int i = 0; i < 8; i++)
                #pragma unroll
                for (int j = 0; j < 8; j++)
                    acc[i][j] += a[i] * b[j];
        }
        __syncthreads();
    }

    // ---- epilogue: add bias, scatter to NCHW ----
    #pragma unroll
    for (int i = 0; i < 8; i++) {
        const int m  = (i < 4) ? (ty * 4 + i) : (64 + ty * 4 + (i - 4));
        const int oc = oc0 + m;
        const float bv = __ldg(&bias[oc]);
        #pragma unroll
        for (int j = 0; j < 8; j++) {
            const int col = (j < 4) ? (tx * 4 + j) : (64 + tx * 4 + (j - 4));
            const int pg  = pix0 + col;
            const int n   = pg / HW_IMG;
            const int hw  = pg - n * HW_IMG;
            out[((long long)n * 256 + oc) * HW_IMG + hw] = acc[i][j] + bv;
        }
    }
}

extern "C" void kernel_launch(void* const* d_in, const int* in_sizes, int n_in,
                              void* d_out, int out_size)
{
    const float* x    = (const float*)d_in[0];   // [32,128,56,56]
    const float* wgt  = (const float*)d_in[1];   // [256,128,3,3]
    const float* bias = (const float*)d_in[2];   // [256]
    float* out        = (float*)d_out;           // [32,256,56,56]

    dim3 grid(100352 / BN, 256 / BM);            // (784, 2)
    conv_igemm_kernel<<<grid, 256>>>(x, wgt, bias, out);
}

// round 3
// speedup vs baseline: 1.5267x; 1.5267x over previous
#include <cuda_runtime.h>
#include <cuda_bf16.h>
#include <cstdint>

// Implicit-GEMM conv via mma.sync bf16x3 (hi/lo split, 3 accumulation passes).
// GEMM: M=256(oc) x N=100352(pix) x K=1152. CTA tile 128x128, BK=32.
// 8 warps in 2(M) x 4(N): warp tile 64x32 = 4x4 m16n8k16 tiles.

#define C_IN   128
#define HWI    3136
#define KDIM   1152
#define BK     32
#define NCHUNK (KDIM / BK)   // 36
#define LROW   40            // smem row pitch in bf16 (32 data + 8 pad) = 80B

static __device__ __forceinline__ uint32_t s2u(const void* p) {
    uint32_t a;
    asm("{ .reg .u64 t; cvta.to.shared.u64 t, %1; cvt.u32.u64 %0, t; }" : "=r"(a) : "l"(p));
    return a;
}

static __device__ __forceinline__ void ldsm4(uint32_t& r0, uint32_t& r1,
                                             uint32_t& r2, uint32_t& r3, uint32_t addr) {
    asm volatile("ldmatrix.sync.aligned.m8n8.x4.shared.b16 {%0,%1,%2,%3}, [%4];"
                 : "=r"(r0), "=r"(r1), "=r"(r2), "=r"(r3) : "r"(addr));
}

static __device__ __forceinline__ void mma16816(float* c, const uint32_t* a,
                                                uint32_t b0, uint32_t b1) {
    asm volatile(
        "mma.sync.aligned.m16n8k16.row.col.f32.bf16.bf16.f32 "
        "{%0,%1,%2,%3}, {%4,%5,%6,%7}, {%8,%9}, {%0,%1,%2,%3};"
        : "+f"(c[0]), "+f"(c[1]), "+f"(c[2]), "+f"(c[3])
        : "r"(a[0]), "r"(a[1]), "r"(a[2]), "r"(a[3]), "r"(b0), "r"(b1));
}

// split two floats into packed bf16x2 hi and lo words
static __device__ __forceinline__ void split2(float f0, float f1, uint32_t& hi, uint32_t& lo) {
    __nv_bfloat16 h0 = __float2bfloat16_rn(f0);
    __nv_bfloat16 h1 = __float2bfloat16_rn(f1);
    __nv_bfloat16 l0 = __float2bfloat16_rn(f0 - __bfloat162float(h0));
    __nv_bfloat16 l1 = __float2bfloat16_rn(f1 - __bfloat162float(h1));
    __nv_bfloat162 hp = __halves2bfloat162(h0, h1);
    __nv_bfloat162 lp = __halves2bfloat162(l0, l1);
    hi = *(uint32_t*)&hp;
    lo = *(uint32_t*)&lp;
}

__global__ __launch_bounds__(256, 1)
void conv_mma_kernel(const float* __restrict__ x,
                     const float* __restrict__ w,
                     const float* __restrict__ bias,
                     float* __restrict__ out)
{
    __shared__ __align__(16) __nv_bfloat16 sAhi[128 * LROW];
    __shared__ __align__(16) __nv_bfloat16 sAlo[128 * LROW];
    __shared__ __align__(16) __nv_bfloat16 sBhi[128 * LROW];
    __shared__ __align__(16) __nv_bfloat16 sBlo[128 * LROW];

    const int tid  = threadIdx.x;
    const int lane = tid & 31;
    const int wid  = tid >> 5;

    const int oc0  = blockIdx.x * 128;   // 2 oc-blocks: fast dim -> same pixels adjacent in L2
    const int pix0 = blockIdx.y * 128;

    // ---- fill roles: thread owns one row (oc for A / pixel for B), one 16-k half ----
    const int rowF = tid & 127;
    const int half = tid >> 7;
    const int pixg = pix0 + rowF;
    const int nimg_b = pixg / HWI;
    const int hw_b   = pixg - nimg_b * HWI;
    const int oh = hw_b / 56;
    const int ow = hw_b - oh * 56;
    const float* __restrict__ xn = x + (size_t)nimg_b * C_IN * HWI;
    const float* __restrict__ wrow = w + (size_t)(oc0 + rowF) * KDIM + half * 16;

    // ---- warp tile coords: wm in {0,1} (64 oc), wn in {0..3} (32 pix) ----
    const int wm = wid & 1;
    const int wn = wid >> 1;

    // ldmatrix lane addressing (bytes); row pitch = 80B
    const int aRow = lane & 15;
    const int aSel = lane >> 4;
    const uint32_t aOffB = (uint32_t)((wm * 64 + aRow) * 80 + aSel * 16);
    const uint32_t aHiBase = s2u(sAhi) + aOffB;
    const uint32_t aLoBase = s2u(sAlo) + aOffB;

    const int bRow = ((lane >> 4) << 3) | (lane & 7);
    const int bSel = (lane >> 3) & 1;
    const uint32_t bOffB = (uint32_t)((wn * 32 + bRow) * 80 + bSel * 16);
    const uint32_t bHiBase = s2u(sBhi) + bOffB;
    const uint32_t bLoBase = s2u(sBlo) + bOffB;

    float acc[4][4][4];
    #pragma unroll
    for (int i = 0; i < 4; i++)
        #pragma unroll
        for (int j = 0; j < 4; j++)
            #pragma unroll
            for (int q = 0; q < 4; q++)
                acc[i][j][q] = 0.0f;

    const uint32_t sRowOff = (uint32_t)(rowF * 80 + half * 32);   // byte offset of this thread's fill slot

    #pragma unroll 1
    for (int chunk = 0; chunk < NCHUNK; ++chunk) {
        const int k0 = chunk * BK;

        // ---- A fill: 16 weights -> hi/lo bf16 ----
        {
            const float4* w4 = (const float4*)(wrow + k0);
            float4 v0 = w4[0], v1 = w4[1], v2 = w4[2], v3 = w4[3];
            uint4 h0, l0, h1, l1;
            split2(v0.x, v0.y, h0.x, l0.x);
            split2(v0.z, v0.w, h0.y, l0.y);
            split2(v1.x, v1.y, h0.z, l0.z);
            split2(v1.z, v1.w, h0.w, l0.w);
            split2(v2.x, v2.y, h1.x, l1.x);
            split2(v2.z, v2.w, h1.y, l1.y);
            split2(v3.x, v3.y, h1.z, l1.z);
            split2(v3.z, v3.w, h1.w, l1.w);
            char* pA = (char*)sAhi + sRowOff;
            char* pL = (char*)sAlo + sRowOff;
            ((uint4*)pA)[0] = h0; ((uint4*)pA)[1] = h1;
            ((uint4*)pL)[0] = l0; ((uint4*)pL)[1] = l1;
        }
        // ---- B fill: im2col gather, 16 k values for this pixel ----
        {
            float f[16];
            #pragma unroll
            for (int e = 0; e < 16; ++e) {
                const int kk = k0 + half * 16 + e;
                const int c  = kk / 9;
                const int rs = kk - c * 9;
                const int r  = rs / 3;
                const int s  = rs - r * 3;
                const int ih = oh + r - 1;
                const int iw = ow + s - 1;
                float v = 0.0f;
                if ((unsigned)ih < 56u && (unsigned)iw < 56u)
                    v = xn[(c * 56 + ih) * 56 + iw];
                f[e] = v;
            }
            uint4 h0, l0, h1, l1;
            split2(f[0],  f[1],  h0.x, l0.x);
            split2(f[2],  f[3],  h0.y, l0.y);
            split2(f[4],  f[5],  h0.z, l0.z);
            split2(f[6],  f[7],  h0.w, l0.w);
            split2(f[8],  f[9],  h1.x, l1.x);
            split2(f[10], f[11], h1.y, l1.y);
            split2(f[12], f[13], h1.z, l1.z);
            split2(f[14], f[15], h1.w, l1.w);
            char* pB = (char*)sBhi + sRowOff;
            char* pL = (char*)sBlo + sRowOff;
            ((uint4*)pB)[0] = h0; ((uint4*)pB)[1] = h1;
            ((uint4*)pL)[0] = l0; ((uint4*)pL)[1] = l1;
        }

        __syncthreads();

        // ---- MMA: 2 k16 steps, 3 passes each ----
        #pragma unroll
        for (int ks = 0; ks < 2; ++ks) {
            const uint32_t kOff = (uint32_t)(ks * 32);
            uint32_t ah[4][4], al[4][4], bh[8], bl[8];
            #pragma unroll
            for (int mt = 0; mt < 4; ++mt) {
                ldsm4(ah[mt][0], ah[mt][1], ah[mt][2], ah[mt][3],
                      aHiBase + kOff + (uint32_t)(mt * 16 * 80));
                ldsm4(al[mt][0], al[mt][1], al[mt][2], al[mt][3],
                      aLoBase + kOff + (uint32_t)(mt * 16 * 80));
            }
            #pragma unroll
            for (int nb = 0; nb < 2; ++nb) {
                ldsm4(bh[nb * 4 + 0], bh[nb * 4 + 1], bh[nb * 4 + 2], bh[nb * 4 + 3],
                      bHiBase + kOff + (uint32_t)(nb * 16 * 80));
                ldsm4(bl[nb * 4 + 0], bl[nb * 4 + 1], bl[nb * 4 + 2], bl[nb * 4 + 3],
                      bLoBase + kOff + (uint32_t)(nb * 16 * 80));
            }
            #pragma unroll
            for (int mt = 0; mt < 4; ++mt) {
                #pragma unroll
                for (int nt = 0; nt < 4; ++nt) {
                    float* c = acc[mt][nt];
                    const uint32_t b0h = bh[nt * 2 + 0], b1h = bh[nt * 2 + 1];
                    const uint32_t b0l = bl[nt * 2 + 0], b1l = bl[nt * 2 + 1];
                    mma16816(c, ah[mt], b0h, b1h);   // hi * hi
                    mma16816(c, ah[mt], b0l, b1l);   // hi * lo
                    mma16816(c, al[mt], b0h, b1h);   // lo * hi
                }
            }
        }

        __syncthreads();
    }

    // ---- epilogue: registers -> global, float2 stores along pixel dim ----
    #pragma unroll
    for (int mt = 0; mt < 4; ++mt) {
        const int r0 = oc0 + wm * 64 + mt * 16 + (lane >> 2);
        const int r1 = r0 + 8;
        const float bv0 = __ldg(&bias[r0]);
        const float bv1 = __ldg(&bias[r1]);
        #pragma unroll
        for (int nt = 0; nt < 4; ++nt) {
            const int pg   = pix0 + wn * 32 + nt * 8 + (lane & 3) * 2;
            const int nimg = pg / HWI;
            const int hw   = pg - nimg * HWI;
            const float* c = acc[mt][nt];
            float2 v0 = make_float2(c[0] + bv0, c[1] + bv0);
            float2 v1 = make_float2(c[2] + bv1, c[3] + bv1);
            *(float2*)&out[((size_t)nimg * 256 + r0) * HWI + hw] = v0;
            *(float2*)&out[((size_t)nimg * 256 + r1) * HWI + hw] = v1;
        }
    }
}

extern "C" void kernel_launch(void* const* d_in, const int* in_sizes, int n_in,
                              void* d_out, int out_size)
{
    const float* x    = (const float*)d_in[0];   // [32,128,56,56]
    const float* wgt  = (const float*)d_in[1];   // [256,128,3,3]
    const float* bias = (const float*)d_in[2];   // [256]
    float* out        = (float*)d_out;           // [32,256,56,56]

    dim3 grid(2, 784);                           // oc fast, pixel slow
    conv_mma_kernel<<<grid, 256>>>(x, wgt, bias, out);
}

// round 4
// speedup vs baseline: 1.8338x; 1.2012x over previous
#include <cuda_runtime.h>
#include <cuda_bf16.h>
#include <cstdint>

// Implicit-GEMM conv via mma.sync bf16x3, double-buffered, 512 threads.
// GEMM: M=256(oc) x N=100352(pix) x K=1152. CTA tile 128x128, BK=32.
// 16 warps in 4(M) x 4(N): warp tile 32x32 = 2x4 m16n8k16 tiles, 3 passes.

#define C_IN   128
#define HWI    3136
#define KDIM   1152
#define BK     32
#define NCHUNK (KDIM / BK)   // 36

// smem: one buffer = 4 tiles x 128 rows x 80B (32 bf16 + 8 pad) = 40960 B; x2 buffers
#define TILE_B   10240
#define OFF_AHI  0
#define OFF_ALO  10240
#define OFF_BHI  20480
#define OFF_BLO  30720
#define BUF_B    40960
#define SMEM_TOTAL (2 * BUF_B)   // 81920

static __device__ __forceinline__ uint32_t s2u(const void* p) {
    uint32_t a;
    asm("{ .reg .u64 t; cvta.to.shared.u64 t, %1; cvt.u32.u64 %0, t; }" : "=r"(a) : "l"(p));
    return a;
}

static __device__ __forceinline__ void ldsm4(uint32_t& r0, uint32_t& r1,
                                             uint32_t& r2, uint32_t& r3, uint32_t addr) {
    asm volatile("ldmatrix.sync.aligned.m8n8.x4.shared.b16 {%0,%1,%2,%3}, [%4];"
                 : "=r"(r0), "=r"(r1), "=r"(r2), "=r"(r3) : "r"(addr));
}

static __device__ __forceinline__ void mma16816(float* c, const uint32_t* a,
                                                uint32_t b0, uint32_t b1) {
    asm volatile(
        "mma.sync.aligned.m16n8k16.row.col.f32.bf16.bf16.f32 "
        "{%0,%1,%2,%3}, {%4,%5,%6,%7}, {%8,%9}, {%0,%1,%2,%3};"
        : "+f"(c[0]), "+f"(c[1]), "+f"(c[2]), "+f"(c[3])
        : "r"(a[0]), "r"(a[1]), "r"(a[2]), "r"(a[3]), "r"(b0), "r"(b1));
}

static __device__ __forceinline__ void split2(float f0, float f1, uint32_t& hi, uint32_t& lo) {
    __nv_bfloat16 h0 = __float2bfloat16_rn(f0);
    __nv_bfloat16 h1 = __float2bfloat16_rn(f1);
    __nv_bfloat16 l0 = __float2bfloat16_rn(f0 - __bfloat162float(h0));
    __nv_bfloat16 l1 = __float2bfloat16_rn(f1 - __bfloat162float(h1));
    __nv_bfloat162 hp = __halves2bfloat162(h0, h1);
    __nv_bfloat162 lp = __halves2bfloat162(l0, l1);
    hi = *(uint32_t*)&hp;
    lo = *(uint32_t*)&lp;
}

__global__ __launch_bounds__(512, 1)
void conv_mma2_kernel(const float* __restrict__ x,
                      const float* __restrict__ w,
                      const float* __restrict__ bias,
                      float* __restrict__ out)
{
    extern __shared__ __align__(16) char smem[];

    const int tid  = threadIdx.x;
    const int lane = tid & 31;
    const int wid  = tid >> 5;

    const int oc0  = blockIdx.x * 128;
    const int pix0 = blockIdx.y * 128;

    // ---- fill roles: thread owns one row, one 8-k quarter of the 32-k chunk ----
    const int rowF = tid & 127;
    const int q    = tid >> 7;                  // 0..3
    const int pixg = pix0 + rowF;
    const int nimg_b = pixg / HWI;
    const int hw_b   = pixg - nimg_b * HWI;
    const int oh = hw_b / 56;
    const int ow = hw_b - oh * 56;
    const float* __restrict__ xn = x + (size_t)nimg_b * C_IN * HWI;
    const float* __restrict__ wrow = w + (size_t)(oc0 + rowF) * KDIM + q * 8;
    const uint32_t sRowOff = (uint32_t)(rowF * 80 + q * 16);   // bytes

    // ---- warp tile: wm in {0..3} (32 oc), wn in {0..3} (32 pix) ----
    const int wm = wid & 3;
    const int wn = wid >> 2;

    const uint32_t sbase = s2u(smem);
    const int aRow = lane & 15;
    const int aSel = lane >> 4;
    const uint32_t aOffB = (uint32_t)((wm * 32 + aRow) * 80 + aSel * 16);
    const int bRow = ((lane >> 4) << 3) | (lane & 7);
    const int bSel = (lane >> 3) & 1;
    const uint32_t bOffB = (uint32_t)((wn * 32 + bRow) * 80 + bSel * 16);

    float acc[2][4][4];
    #pragma unroll
    for (int i = 0; i < 2; i++)
        #pragma unroll
        for (int j = 0; j < 4; j++)
            #pragma unroll
            for (int p = 0; p < 4; p++)
                acc[i][j][p] = 0.0f;

    // ---- prefetch + convert + store for a chunk ----
    float4 pfA0, pfA1;                 // 8 weights
    float  pfB[8];                     // 8 im2col values

    // load chunk 0
    {
        const float4* w4 = (const float4*)wrow;
        pfA0 = w4[0]; pfA1 = w4[1];
        #pragma unroll
        for (int e = 0; e < 8; ++e) {
            const int kk = q * 8 + e;
            const int c  = kk / 9;
            const int rs = kk - c * 9;
            const int r  = rs / 3;
            const int s  = rs - r * 3;
            const int ih = oh + r - 1;
            const int iw = ow + s - 1;
            float v = 0.0f;
            if ((unsigned)ih < 56u && (unsigned)iw < 56u)
                v = xn[(c * 56 + ih) * 56 + iw];
            pfB[e] = v;
        }
    }
    // convert + store chunk 0 into buf 0
    {
        uint4 hi, lo;
        split2(pfA0.x, pfA0.y, hi.x, lo.x);
        split2(pfA0.z, pfA0.w, hi.y, lo.y);
        split2(pfA1.x, pfA1.y, hi.z, lo.z);
        split2(pfA1.z, pfA1.w, hi.w, lo.w);
        *(uint4*)(smem + OFF_AHI + sRowOff) = hi;
        *(uint4*)(smem + OFF_ALO + sRowOff) = lo;
        split2(pfB[0], pfB[1], hi.x, lo.x);
        split2(pfB[2], pfB[3], hi.y, lo.y);
        split2(pfB[4], pfB[5], hi.z, lo.z);
        split2(pfB[6], pfB[7], hi.w, lo.w);
        *(uint4*)(smem + OFF_BHI + sRowOff) = hi;
        *(uint4*)(smem + OFF_BLO + sRowOff) = lo;
    }
    __syncthreads();

    #pragma unroll 1
    for (int chunk = 0; chunk < NCHUNK; ++chunk) {
        const int cur = chunk & 1;
        const int nxt = cur ^ 1;

        // ---- issue global loads for chunk+1 (latency overlaps MMA below) ----
        if (chunk + 1 < NCHUNK) {
            const int k0 = (chunk + 1) * BK;
            const float4* w4 = (const float4*)(wrow + k0);
            pfA0 = w4[0]; pfA1 = w4[1];
            #pragma unroll
            for (int e = 0; e < 8; ++e) {
                const int kk = k0 + q * 8 + e;
                const int c  = kk / 9;
                const int rs = kk - c * 9;
                const int r  = rs / 3;
                const int s  = rs - r * 3;
                const int ih = oh + r - 1;
                const int iw = ow + s - 1;
                float v = 0.0f;
                if ((unsigned)ih < 56u && (unsigned)iw < 56u)
                    v = xn[(c * 56 + ih) * 56 + iw];
                pfB[e] = v;
            }
        }

        // ---- MMA from buf cur: 2 k16 steps x (2x4 tiles) x 3 passes ----
        const uint32_t bufB = sbase + (uint32_t)(cur * BUF_B);
        #pragma unroll
        for (int ks = 0; ks < 2; ++ks) {
            const uint32_t kOff = (uint32_t)(ks * 32);
            uint32_t ah[2][4], al[2][4], bh[8], bl[8];
            #pragma unroll
            for (int mt = 0; mt < 2; ++mt) {
                const uint32_t ao = bufB + aOffB + kOff + (uint32_t)(mt * 16 * 80);
                ldsm4(ah[mt][0], ah[mt][1], ah[mt][2], ah[mt][3], ao + OFF_AHI);
                ldsm4(al[mt][0], al[mt][1], al[mt][2], al[mt][3], ao + OFF_ALO);
            }
            #pragma unroll
            for (int nb = 0; nb < 2; ++nb) {
                const uint32_t bo = bufB + bOffB + kOff + (uint32_t)(nb * 16 * 80);
                ldsm4(bh[nb*4+0], bh[nb*4+1], bh[nb*4+2], bh[nb*4+3], bo + OFF_BHI);
                ldsm4(bl[nb*4+0], bl[nb*4+1], bl[nb*4+2], bl[nb*4+3], bo + OFF_BLO);
            }
            #pragma unroll
            for (int mt = 0; mt < 2; ++mt) {
                #pragma unroll
                for (int nt = 0; nt < 4; ++nt) {
                    float* c = acc[mt][nt];
                    const uint32_t b0h = bh[nt*2], b1h = bh[nt*2+1];
                    const uint32_t b0l = bl[nt*2], b1l = bl[nt*2+1];
                    mma16816(c, ah[mt], b0h, b1h);
                    mma16816(c, ah[mt], b0l, b1l);
                    mma16816(c, al[mt], b0h, b1h);
                }
            }
        }

        // ---- convert + store chunk+1 into buf nxt ----
        if (chunk + 1 < NCHUNK) {
            char* base = smem + nxt * BUF_B;
            uint4 hi, lo;
            split2(pfA0.x, pfA0.y, hi.x, lo.x);
            split2(pfA0.z, pfA0.w, hi.y, lo.y);
            split2(pfA1.x, pfA1.y, hi.z, lo.z);
            split2(pfA1.z, pfA1.w, hi.w, lo.w);
            *(uint4*)(base + OFF_AHI + sRowOff) = hi;
            *(uint4*)(base + OFF_ALO + sRowOff) = lo;
            split2(pfB[0], pfB[1], hi.x, lo.x);
            split2(pfB[2], pfB[3], hi.y, lo.y);
            split2(pfB[4], pfB[5], hi.z, lo.z);
            split2(pfB[6], pfB[7], hi.w, lo.w);
            *(uint4*)(base + OFF_BHI + sRowOff) = hi;
            *(uint4*)(base + OFF_BLO + sRowOff) = lo;
        }
        __syncthreads();
    }

    // ---- epilogue ----
    #pragma unroll
    for (int mt = 0; mt < 2; ++mt) {
        const int r0 = oc0 + wm * 32 + mt * 16 + (lane >> 2);
        const int r1 = r0 + 8;
        const float bv0 = __ldg(&bias[r0]);
        const float bv1 = __ldg(&bias[r1]);
        #pragma unroll
        for (int nt = 0; nt < 4; ++nt) {
            const int pg   = pix0 + wn * 32 + nt * 8 + (lane & 3) * 2;
            const int nimg = pg / HWI;
            const int hw   = pg - nimg * HWI;
            const float* c = acc[mt][nt];
            float2 v0 = make_float2(c[0] + bv0, c[1] + bv0);
            float2 v1 = make_float2(c[2] + bv1, c[3] + bv1);
            *(float2*)&out[((size_t)nimg * 256 + r0) * HWI + hw] = v0;
            *(float2*)&out[((size_t)nimg * 256 + r1) * HWI + hw] = v1;
        }
    }
}

extern "C" void kernel_launch(void* const* d_in, const int* in_sizes, int n_in,
                              void* d_out, int out_size)
{
    const float* x    = (const float*)d_in[0];   // [32,128,56,56]
    const float* wgt  = (const float*)d_in[1];   // [256,128,3,3]
    const float* bias = (const float*)d_in[2];   // [256]
    float* out        = (float*)d_out;           // [32,256,56,56]

    cudaFuncSetAttribute(conv_mma2_kernel,
                         cudaFuncAttributeMaxDynamicSharedMemorySize, SMEM_TOTAL);

    dim3 grid(2, 784);                           // oc fast, pixel slow
    conv_mma2_kernel<<<grid, 512, SMEM_TOTAL>>>(x, wgt, bias, out);
}

// round 5
// speedup vs baseline: 2.4346x; 1.3276x over previous
#include <cuda_runtime.h>
#include <cuda_fp16.h>
#include <cstdint>

// Conv as implicit GEMM, fp16 2-pass split (A = whi+wlo, B = fp16(x im2col)),
// fp32 accumulate. Pre-kernels build fp16 operands once per launch; main kernel
// is a pure GEMM: cp.async double-buffered fills + ldmatrix + mma.sync.
// M=256(oc) x N=100352(pix) x K=1152. CTA 256x128, 8 warps, warp tile 64x64.

#define C_IN   128
#define HWI    3136
#define NPIX   100352
#define KDIM   1152
#define BK     32
#define NCHUNK 36
#define PITCH  80         // smem row pitch bytes (64B data + 16 pad)

#define OFF_AHI 0
#define OFF_ALO 20480     // 256*80
#define OFF_B   40960
#define BUF_B   51200     // + 128*80
#define SMEM_TOTAL (2 * BUF_B)   // 102400

__device__ __align__(16) __half g_whi[256 * KDIM];
__device__ __align__(16) __half g_wlo[256 * KDIM];
__device__ __align__(16) __half g_bcol[(size_t)NPIX * KDIM];   // ~231 MB

static __device__ __forceinline__ uint32_t s2u(const void* p) {
    uint32_t a;
    asm("{ .reg .u64 t; cvta.to.shared.u64 t, %1; cvt.u32.u64 %0, t; }" : "=r"(a) : "l"(p));
    return a;
}

static __device__ __forceinline__ void cp16(uint32_t dst, const void* src) {
    asm volatile("cp.async.cg.shared.global [%0], [%1], 16;" :: "r"(dst), "l"(src));
}

static __device__ __forceinline__ void ldsm4(uint32_t* r, uint32_t addr) {
    asm volatile("ldmatrix.sync.aligned.m8n8.x4.shared.b16 {%0,%1,%2,%3}, [%4];"
                 : "=r"(r[0]), "=r"(r[1]), "=r"(r[2]), "=r"(r[3]) : "r"(addr));
}

static __device__ __forceinline__ void mma16816(float* c, const uint32_t* a,
                                                uint32_t b0, uint32_t b1) {
    asm volatile(
        "mma.sync.aligned.m16n8k16.row.col.f32.f16.f16.f32 "
        "{%0,%1,%2,%3}, {%4,%5,%6,%7}, {%8,%9}, {%0,%1,%2,%3};"
        : "+f"(c[0]), "+f"(c[1]), "+f"(c[2]), "+f"(c[3])
        : "r"(a[0]), "r"(a[1]), "r"(a[2]), "r"(a[3]), "r"(b0), "r"(b1));
}

// ---------- pre-kernel 1: weights fp32 -> fp16 hi/lo ----------
__global__ void prep_w(const float* __restrict__ w) {
    const int i = blockIdx.x * 256 + threadIdx.x;     // 36864 threads, 8 elems each
    const float4* w4 = (const float4*)w;
    float4 a = w4[i * 2], b = w4[i * 2 + 1];
    __half hi[8], lo[8];
    float f[8] = {a.x, a.y, a.z, a.w, b.x, b.y, b.z, b.w};
    #pragma unroll
    for (int e = 0; e < 8; ++e) {
        hi[e] = __float2half_rn(f[e]);
        lo[e] = __float2half_rn(f[e] - __half2float(hi[e]));
    }
    *(uint4*)&g_whi[i * 8] = *(uint4*)hi;
    *(uint4*)&g_wlo[i * 8] = *(uint4*)lo;
}

// ---------- pre-kernel 2: im2col + fp32->fp16, B[pix][k] k-contiguous ----------
__global__ void prep_im2col(const float* __restrict__ x) {
    const int gid = blockIdx.x * 256 + threadIdx.x;   // NPIX*144 = 14,450,688
    if (gid >= NPIX * (KDIM / 8)) return;
    const int pix = gid / (KDIM / 8);
    const int seg = gid - pix * (KDIM / 8);
    const int n  = pix / HWI;
    const int hw = pix - n * HWI;
    const int oh = hw / 56;
    const int ow = hw - oh * 56;
    const float* __restrict__ xn = x + (size_t)n * C_IN * HWI;
    const int k0 = seg * 8;
    __half h[8];
    #pragma unroll
    for (int e = 0; e < 8; ++e) {
        const int kk = k0 + e;
        const int c  = kk / 9;
        const int rs = kk - c * 9;
        const int r  = rs / 3;
        const int s  = rs - r * 3;
        const int ih = oh + r - 1;
        const int iw = ow + s - 1;
        float v = 0.0f;
        if ((unsigned)ih < 56u && (unsigned)iw < 56u)
            v = xn[(c * 56 + ih) * 56 + iw];
        h[e] = __float2half_rn(v);
    }
    *(uint4*)&g_bcol[(size_t)pix * KDIM + k0] = *(uint4*)h;
}

// ---------- main GEMM kernel ----------
__global__ __launch_bounds__(256, 1)
void conv_main(const float* __restrict__ bias, float* __restrict__ out)
{
    extern __shared__ __align__(16) char smem[];
    const uint32_t sb = s2u(smem);

    const int tid  = threadIdx.x;
    const int lane = tid & 31;
    const int wid  = tid >> 5;
    const int pix0 = blockIdx.x * 128;

    const int wm = wid & 3;       // M: 4 x 64
    const int wn = wid >> 2;      // N: 2 x 64

    // ---- cp.async chore addresses (byte offsets, k0-relative added per chunk) ----
    // A: 1024 x 16B chores (hi) : chore = tid + 256*i, row=chore>>2 (0..255), seg=chore&3
    // B: 512 x 16B chores       : row = chore>>2 (0..127)
    uint32_t aDst[4], bDst[2];
    uint64_t aSrc[4], bSrc[2];    // byte offset into g_whi / g_bcol (excluding k0)
    #pragma unroll
    for (int i = 0; i < 4; ++i) {
        const int ch = tid + 256 * i;
        const int row = ch >> 2, seg = ch & 3;
        aDst[i] = (uint32_t)(row * PITCH + seg * 16);
        aSrc[i] = (uint64_t)(row * KDIM + seg * 8) * 2;
    }
    #pragma unroll
    for (int i = 0; i < 2; ++i) {
        const int ch = tid + 256 * i;
        const int row = ch >> 2, seg = ch & 3;
        bDst[i] = (uint32_t)(row * PITCH + seg * 16);
        bSrc[i] = ((uint64_t)(pix0 + row) * KDIM + seg * 8) * 2;
    }
    const char* whiB = (const char*)g_whi;
    const char* wloB = (const char*)g_wlo;
    const char* bcolB = (const char*)g_bcol;

    // ---- ldmatrix lane addressing ----
    const uint32_t aOffB = (uint32_t)((wm * 64 + (lane & 15)) * PITCH + (lane >> 4) * 16);
    const int bRow = ((lane >> 4) << 3) | (lane & 7);
    const int bSel = (lane >> 3) & 1;
    const uint32_t bOffB = (uint32_t)((wn * 64 + bRow) * PITCH + bSel * 16);

    float acc[4][8][4];
    #pragma unroll
    for (int i = 0; i < 4; i++)
        #pragma unroll
        for (int j = 0; j < 8; j++)
            #pragma unroll
            for (int q = 0; q < 4; q++)
                acc[i][j][q] = 0.0f;

    // ---- prologue: fill buffer 0 with chunk 0 ----
    {
        const uint64_t kB = 0;
        #pragma unroll
        for (int i = 0; i < 4; ++i) {
            cp16(sb + OFF_AHI + aDst[i], whiB + aSrc[i] + kB);
            cp16(sb + OFF_ALO + aDst[i], wloB + aSrc[i] + kB);
        }
        #pragma unroll
        for (int i = 0; i < 2; ++i)
            cp16(sb + OFF_B + bDst[i], bcolB + bSrc[i] + kB);
        asm volatile("cp.async.commit_group;" ::: "memory");
        asm volatile("cp.async.wait_group 0;" ::: "memory");
    }
    __syncthreads();

    #pragma unroll 1
    for (int chunk = 0; chunk < NCHUNK; ++chunk) {
        const int cur = chunk & 1;
        const uint32_t bufS = sb + (uint32_t)(cur * BUF_B);

        // ---- issue cp.async for chunk+1 into other buffer ----
        if (chunk + 1 < NCHUNK) {
            const uint32_t nb = sb + (uint32_t)((cur ^ 1) * BUF_B);
            const uint64_t kB = (uint64_t)(chunk + 1) * BK * 2;
            #pragma unroll
            for (int i = 0; i < 4; ++i) {
                cp16(nb + OFF_AHI + aDst[i], whiB + aSrc[i] + kB);
                cp16(nb + OFF_ALO + aDst[i], wloB + aSrc[i] + kB);
            }
            #pragma unroll
            for (int i = 0; i < 2; ++i)
                cp16(nb + OFF_B + bDst[i], bcolB + bSrc[i] + kB);
            asm volatile("cp.async.commit_group;" ::: "memory");
        }

        // ---- MMA: 2 k16 steps x (4x8 tiles) x 2 passes ----
        #pragma unroll
        for (int ks = 0; ks < 2; ++ks) {
            const uint32_t ko = (uint32_t)(ks * 32);
            uint32_t bf[16];
            #pragma unroll
            for (int nb4 = 0; nb4 < 4; ++nb4)
                ldsm4(&bf[nb4 * 4], bufS + OFF_B + bOffB + ko + (uint32_t)(nb4 * 16 * PITCH));
            uint32_t af[16];
            #pragma unroll
            for (int mt = 0; mt < 4; ++mt)
                ldsm4(&af[mt * 4], bufS + OFF_AHI + aOffB + ko + (uint32_t)(mt * 16 * PITCH));
            #pragma unroll
            for (int mt = 0; mt < 4; ++mt)
                #pragma unroll
                for (int nt = 0; nt < 8; ++nt)
                    mma16816(acc[mt][nt], &af[mt * 4], bf[nt * 2], bf[nt * 2 + 1]);
            #pragma unroll
            for (int mt = 0; mt < 4; ++mt)
                ldsm4(&af[mt * 4], bufS + OFF_ALO + aOffB + ko + (uint32_t)(mt * 16 * PITCH));
            #pragma unroll
            for (int mt = 0; mt < 4; ++mt)
                #pragma unroll
                for (int nt = 0; nt < 8; ++nt)
                    mma16816(acc[mt][nt], &af[mt * 4], bf[nt * 2], bf[nt * 2 + 1]);
        }

        asm volatile("cp.async.wait_group 0;" ::: "memory");
        __syncthreads();
    }

    // ---- epilogue ----
    #pragma unroll
    for (int mt = 0; mt < 4; ++mt) {
        const int r0 = wm * 64 + mt * 16 + (lane >> 2);
        const int r1 = r0 + 8;
        const float bv0 = __ldg(&bias[r0]);
        const float bv1 = __ldg(&bias[r1]);
        #pragma unroll
        for (int nt = 0; nt < 8; ++nt) {
            const int pg   = pix0 + wn * 64 + nt * 8 + (lane & 3) * 2;
            const int nimg = pg / HWI;
            const int hw   = pg - nimg * HWI;
            const float* c = acc[mt][nt];
            float2 v0 = make_float2(c[0] + bv0, c[1] + bv0);
            float2 v1 = make_float2(c[2] + bv1, c[3] + bv1);
            *(float2*)&out[((size_t)nimg * 256 + r0) * HWI + hw] = v0;
            *(float2*)&out[((size_t)nimg * 256 + r1) * HWI + hw] = v1;
        }
    }
}

extern "C" void kernel_launch(void* const* d_in, const int* in_sizes, int n_in,
                              void* d_out, int out_size)
{
    const float* x    = (const float*)d_in[0];   // [32,128,56,56]
    const float* wgt  = (const float*)d_in[1];   // [256,128,3,3]
    const float* bias = (const float*)d_in[2];   // [256]
    float* out        = (float*)d_out;           // [32,256,56,56]

    cudaFuncSetAttribute(conv_main,
                         cudaFuncAttributeMaxDynamicSharedMemorySize, SMEM_TOTAL);

    prep_w<<<144, 256>>>(wgt);                          // 256*1152/8 threads
    prep_im2col<<<(NPIX * (KDIM / 8) + 255) / 256, 256>>>(x);
    conv_main<<<NPIX / 128, 256, SMEM_TOTAL>>>(bias, out);
}

// round 6
// speedup vs baseline: 3.4145x; 1.4025x over previous
#include <cuda_runtime.h>
#include <cuda_fp16.h>
#include <cstdint>

// Conv as implicit GEMM, single-pass fp16 (fp32 accumulate).
// Pre-kernels: w -> fp16 [256][1152]; x -> fp16 im2col [100352][1152].
// Main: pure GEMM, 4-stage cp.async ring + ldmatrix + mma.sync m16n8k16.
// M=256(oc) x N=100352(pix) x K=1152. CTA 256x128, 8 warps, warp tile 64x64.

#define C_IN   128
#define HWI    3136
#define NPIX   100352
#define KDIM   1152
#define BK     32
#define NCHUNK 36
#define PITCH  80         // smem row pitch bytes (64B data + 16 pad)

#define OFF_A   0
#define OFF_B   20480     // 256*80
#define STAGE_B 30720     // + 128*80
#define NSTAGE  4
#define SMEM_TOTAL (NSTAGE * STAGE_B)   // 122880

__device__ __align__(16) __half g_wh[256 * KDIM];
__device__ __align__(16) __half g_bcol[(size_t)NPIX * KDIM];   // ~231 MB

static __device__ __forceinline__ uint32_t s2u(const void* p) {
    uint32_t a;
    asm("{ .reg .u64 t; cvta.to.shared.u64 t, %1; cvt.u32.u64 %0, t; }" : "=r"(a) : "l"(p));
    return a;
}

static __device__ __forceinline__ void cp16(uint32_t dst, const void* src) {
    asm volatile("cp.async.cg.shared.global [%0], [%1], 16;" :: "r"(dst), "l"(src));
}

static __device__ __forceinline__ void ldsm4(uint32_t* r, uint32_t addr) {
    asm volatile("ldmatrix.sync.aligned.m8n8.x4.shared.b16 {%0,%1,%2,%3}, [%4];"
                 : "=r"(r[0]), "=r"(r[1]), "=r"(r[2]), "=r"(r[3]) : "r"(addr));
}

static __device__ __forceinline__ void mma16816(float* c, const uint32_t* a,
                                                uint32_t b0, uint32_t b1) {
    asm volatile(
        "mma.sync.aligned.m16n8k16.row.col.f32.f16.f16.f32 "
        "{%0,%1,%2,%3}, {%4,%5,%6,%7}, {%8,%9}, {%0,%1,%2,%3};"
        : "+f"(c[0]), "+f"(c[1]), "+f"(c[2]), "+f"(c[3])
        : "r"(a[0]), "r"(a[1]), "r"(a[2]), "r"(a[3]), "r"(b0), "r"(b1));
}

// ---------- pre-kernel 1: weights fp32 -> fp16 ----------
__global__ void prep_w(const float* __restrict__ w) {
    const int i = blockIdx.x * 256 + threadIdx.x;     // 36864 threads, 8 elems each
    const float4* w4 = (const float4*)w;
    float4 a = w4[i * 2], b = w4[i * 2 + 1];
    float f[8] = {a.x, a.y, a.z, a.w, b.x, b.y, b.z, b.w};
    __half h[8];
    #pragma unroll
    for (int e = 0; e < 8; ++e) h[e] = __float2half_rn(f[e]);
    *(uint4*)&g_wh[i * 8] = *(uint4*)h;
}

// ---------- pre-kernel 2: im2col + fp32->fp16, B[pix][k] ----------
__global__ void prep_im2col(const float* __restrict__ x) {
    const int gid = blockIdx.x * 256 + threadIdx.x;
    if (gid >= NPIX * (KDIM / 8)) return;
    const int pix = gid / (KDIM / 8);
    const int seg = gid - pix * (KDIM / 8);
    const int n  = pix / HWI;
    const int hw = pix - n * HWI;
    const int oh = hw / 56;
    const int ow = hw - oh * 56;
    const float* __restrict__ xn = x + (size_t)n * C_IN * HWI;
    const int k0 = seg * 8;
    __half h[8];
    #pragma unroll
    for (int e = 0; e < 8; ++e) {
        const int kk = k0 + e;
        const int c  = kk / 9;
        const int rs = kk - c * 9;
        const int r  = rs / 3;
        const int s  = rs - r * 3;
        const int ih = oh + r - 1;
        const int iw = ow + s - 1;
        float v = 0.0f;
        if ((unsigned)ih < 56u && (unsigned)iw < 56u)
            v = xn[(c * 56 + ih) * 56 + iw];
        h[e] = __float2half_rn(v);
    }
    *(uint4*)&g_bcol[(size_t)pix * KDIM + k0] = *(uint4*)h;
}

// ---------- main GEMM kernel ----------
__global__ __launch_bounds__(256, 1)
void conv_main(const float* __restrict__ bias, float* __restrict__ out)
{
    extern __shared__ __align__(16) char smem[];
    const uint32_t sb = s2u(smem);

    const int tid  = threadIdx.x;
    const int lane = tid & 31;
    const int wid  = tid >> 5;
    const int pix0 = blockIdx.x * 128;

    const int wm = wid & 3;       // M: 4 x 64
    const int wn = wid >> 2;      // N: 2 x 64

    // ---- cp.async chores: A 1024 x 16B, B 512 x 16B ----
    uint32_t aDst[4], bDst[2];
    uint64_t aSrc[4], bSrc[2];
    #pragma unroll
    for (int i = 0; i < 4; ++i) {
        const int ch = tid + 256 * i;
        const int row = ch >> 2, seg = ch & 3;
        aDst[i] = (uint32_t)(row * PITCH + seg * 16);
        aSrc[i] = (uint64_t)(row * KDIM + seg * 8) * 2;
    }
    #pragma unroll
    for (int i = 0; i < 2; ++i) {
        const int ch = tid + 256 * i;
        const int row = ch >> 2, seg = ch & 3;
        bDst[i] = (uint32_t)(row * PITCH + seg * 16);
        bSrc[i] = ((uint64_t)(pix0 + row) * KDIM + seg * 8) * 2;
    }
    const char* whB  = (const char*)g_wh;
    const char* bcolB = (const char*)g_bcol;

    // ---- ldmatrix lane addressing ----
    const uint32_t aOffB = (uint32_t)((wm * 64 + (lane & 15)) * PITCH + (lane >> 4) * 16);
    const int bRow = ((lane >> 4) << 3) | (lane & 7);
    const int bSel = (lane >> 3) & 1;
    const uint32_t bOffB = (uint32_t)((wn * 64 + bRow) * PITCH + bSel * 16);

    float acc[4][8][4];
    #pragma unroll
    for (int i = 0; i < 4; i++)
        #pragma unroll
        for (int j = 0; j < 8; j++)
            #pragma unroll
            for (int q = 0; q < 4; q++)
                acc[i][j][q] = 0.0f;

    // ---- prologue: fill stages 0..2 ----
    #pragma unroll
    for (int s = 0; s < NSTAGE - 1; ++s) {
        const uint32_t st = sb + (uint32_t)(s * STAGE_B);
        const uint64_t kB = (uint64_t)s * BK * 2;
        #pragma unroll
        for (int i = 0; i < 4; ++i)
            cp16(st + OFF_A + aDst[i], whB + aSrc[i] + kB);
        #pragma unroll
        for (int i = 0; i < 2; ++i)
            cp16(st + OFF_B + bDst[i], bcolB + bSrc[i] + kB);
        asm volatile("cp.async.commit_group;" ::: "memory");
    }

    #pragma unroll 1
    for (int chunk = 0; chunk < NCHUNK; ++chunk) {
        // stage `chunk % 4` is the oldest pending group -> wait for it
        asm volatile("cp.async.wait_group %0;" :: "n"(NSTAGE - 2) : "memory");
        __syncthreads();   // data visible to all; all warps done with chunk-1's stage

        // ---- issue chunk+3 into stage (chunk+3)%4 (== (chunk-1)%4, just freed) ----
        {
            const int cn = chunk + NSTAGE - 1;
            if (cn < NCHUNK) {
                const uint32_t st = sb + (uint32_t)((cn & 3) * STAGE_B);
                const uint64_t kB = (uint64_t)cn * BK * 2;
                #pragma unroll
                for (int i = 0; i < 4; ++i)
                    cp16(st + OFF_A + aDst[i], whB + aSrc[i] + kB);
                #pragma unroll
                for (int i = 0; i < 2; ++i)
                    cp16(st + OFF_B + bDst[i], bcolB + bSrc[i] + kB);
            }
            asm volatile("cp.async.commit_group;" ::: "memory");
        }

        // ---- MMA from stage chunk%4: 2 k16 steps x (4x8 tiles) ----
        const uint32_t bufS = sb + (uint32_t)((chunk & 3) * STAGE_B);
        #pragma unroll
        for (int ks = 0; ks < 2; ++ks) {
            const uint32_t ko = (uint32_t)(ks * 32);
            uint32_t bf[16];
            #pragma unroll
            for (int nb4 = 0; nb4 < 4; ++nb4)
                ldsm4(&bf[nb4 * 4], bufS + OFF_B + bOffB + ko + (uint32_t)(nb4 * 16 * PITCH));
            uint32_t af[16];
            #pragma unroll
            for (int mt = 0; mt < 4; ++mt)
                ldsm4(&af[mt * 4], bufS + OFF_A + aOffB + ko + (uint32_t)(mt * 16 * PITCH));
            #pragma unroll
            for (int mt = 0; mt < 4; ++mt)
                #pragma unroll
                for (int nt = 0; nt < 8; ++nt)
                    mma16816(acc[mt][nt], &af[mt * 4], bf[nt * 2], bf[nt * 2 + 1]);
        }
    }

    // ---- epilogue ----
    #pragma unroll
    for (int mt = 0; mt < 4; ++mt) {
        const int r0 = wm * 64 + mt * 16 + (lane >> 2);
        const int r1 = r0 + 8;
        const float bv0 = __ldg(&bias[r0]);
        const float bv1 = __ldg(&bias[r1]);
        #pragma unroll
        for (int nt = 0; nt < 8; ++nt) {
            const int pg   = pix0 + wn * 64 + nt * 8 + (lane & 3) * 2;
            const int nimg = pg / HWI;
            const int hw   = pg - nimg * HWI;
            const float* c = acc[mt][nt];
            float2 v0 = make_float2(c[0] + bv0, c[1] + bv0);
            float2 v1 = make_float2(c[2] + bv1, c[3] + bv1);
            *(float2*)&out[((size_t)nimg * 256 + r0) * HWI + hw] = v0;
            *(float2*)&out[((size_t)nimg * 256 + r1) * HWI + hw] = v1;
        }
    }
}

extern "C" void kernel_launch(void* const* d_in, const int* in_sizes, int n_in,
                              void* d_out, int out_size)
{
    const float* x    = (const float*)d_in[0];   // [32,128,56,56]
    const float* wgt  = (const float*)d_in[1];   // [256,128,3,3]
    const float* bias = (const float*)d_in[2];   // [256]
    float* out        = (float*)d_out;           // [32,256,56,56]

    cudaFuncSetAttribute(conv_main,
                         cudaFuncAttributeMaxDynamicSharedMemorySize, SMEM_TOTAL);

    prep_w<<<144, 256>>>(wgt);
    prep_im2col<<<(NPIX * (KDIM / 8) + 255) / 256, 256>>>(x);
    conv_main<<<NPIX / 128, 256, SMEM_TOTAL>>>(bias, out);
}

// round 7
// speedup vs baseline: 3.7346x; 1.0938x over previous
#include <cuda_runtime.h>
#include <cuda_fp16.h>
#include <cstdint>

// Conv as implicit GEMM, single-pass fp16 (fp32 accumulate).
// Pre-kernels: w -> fp16 [256][1152]; x -> fp16 im2col [100352][1152].
// Main: pure GEMM, 4-stage cp.async ring + ldmatrix + mma.sync m16n8k16.
// CTA tile 128(oc) x 128(pix), 8 warps (2M x 4N), warp tile 64x32.
// 2 CTAs/SM (regs <= 128, smem 80KB/CTA) for cross-CTA latency hiding.

#define C_IN   128
#define HWI    3136
#define NPIX   100352
#define KDIM   1152
#define BK     32
#define NCHUNK 36
#define PITCH  80         // smem row pitch bytes (64B data + 16 pad)

#define OFF_A   0
#define OFF_B   10240     // 128*80
#define STAGE_B 20480
#define NSTAGE  4
#define SMEM_TOTAL (NSTAGE * STAGE_B)   // 81920

__device__ __align__(16) __half g_wh[256 * KDIM];
__device__ __align__(16) __half g_bcol[(size_t)NPIX * KDIM];   // ~231 MB

static __device__ __forceinline__ uint32_t s2u(const void* p) {
    uint32_t a;
    asm("{ .reg .u64 t; cvta.to.shared.u64 t, %1; cvt.u32.u64 %0, t; }" : "=r"(a) : "l"(p));
    return a;
}

static __device__ __forceinline__ void cp16(uint32_t dst, const void* src) {
    asm volatile("cp.async.cg.shared.global [%0], [%1], 16;" :: "r"(dst), "l"(src));
}

static __device__ __forceinline__ void ldsm4(uint32_t* r, uint32_t addr) {
    asm volatile("ldmatrix.sync.aligned.m8n8.x4.shared.b16 {%0,%1,%2,%3}, [%4];"
                 : "=r"(r[0]), "=r"(r[1]), "=r"(r[2]), "=r"(r[3]) : "r"(addr));
}

static __device__ __forceinline__ void mma16816(float* c, const uint32_t* a,
                                                uint32_t b0, uint32_t b1) {
    asm volatile(
        "mma.sync.aligned.m16n8k16.row.col.f32.f16.f16.f32 "
        "{%0,%1,%2,%3}, {%4,%5,%6,%7}, {%8,%9}, {%0,%1,%2,%3};"
        : "+f"(c[0]), "+f"(c[1]), "+f"(c[2]), "+f"(c[3])
        : "r"(a[0]), "r"(a[1]), "r"(a[2]), "r"(a[3]), "r"(b0), "r"(b1));
}

// ---------- pre-kernel 1: weights fp32 -> fp16 ----------
__global__ void prep_w(const float* __restrict__ w) {
    const int i = blockIdx.x * 256 + threadIdx.x;
    const float4* w4 = (const float4*)w;
    float4 a = w4[i * 2], b = w4[i * 2 + 1];
    float f[8] = {a.x, a.y, a.z, a.w, b.x, b.y, b.z, b.w};
    __half h[8];
    #pragma unroll
    for (int e = 0; e < 8; ++e) h[e] = __float2half_rn(f[e]);
    *(uint4*)&g_wh[i * 8] = *(uint4*)h;
}

// ---------- pre-kernel 2: im2col + fp32->fp16, B[pix][k] ----------
__global__ void prep_im2col(const float* __restrict__ x) {
    const int gid = blockIdx.x * 256 + threadIdx.x;
    if (gid >= NPIX * (KDIM / 8)) return;
    const int pix = gid / (KDIM / 8);
    const int seg = gid - pix * (KDIM / 8);
    const int n  = pix / HWI;
    const int hw = pix - n * HWI;
    const int oh = hw / 56;
    const int ow = hw - oh * 56;
    const float* __restrict__ xn = x + (size_t)n * C_IN * HWI;
    const int k0 = seg * 8;
    __half h[8];
    #pragma unroll
    for (int e = 0; e < 8; ++e) {
        const int kk = k0 + e;
        const int c  = kk / 9;
        const int rs = kk - c * 9;
        const int r  = rs / 3;
        const int s  = rs - r * 3;
        const int ih = oh + r - 1;
        const int iw = ow + s - 1;
        float v = 0.0f;
        if ((unsigned)ih < 56u && (unsigned)iw < 56u)
            v = xn[(c * 56 + ih) * 56 + iw];
        h[e] = __float2half_rn(v);
    }
    *(uint4*)&g_bcol[(size_t)pix * KDIM + k0] = *(uint4*)h;
}

// ---------- main GEMM kernel ----------
__global__ __launch_bounds__(256, 2)
void conv_main(const float* __restrict__ bias, float* __restrict__ out)
{
    extern __shared__ __align__(16) char smem[];
    const uint32_t sb = s2u(smem);

    const int tid  = threadIdx.x;
    const int lane = tid & 31;
    const int wid  = tid >> 5;
    const int oc0  = blockIdx.x * 128;
    const int pix0 = blockIdx.y * 128;

    const int wm = wid & 1;       // M: 2 x 64
    const int wn = wid >> 1;      // N: 4 x 32

    // ---- cp.async chores: A 512 x 16B, B 512 x 16B (2 each per thread) ----
    uint32_t aDst[2], bDst[2];
    uint64_t aSrc[2], bSrc[2];
    #pragma unroll
    for (int i = 0; i < 2; ++i) {
        const int ch = tid + 256 * i;
        const int row = ch >> 2, seg = ch & 3;
        aDst[i] = (uint32_t)(row * PITCH + seg * 16);
        aSrc[i] = (uint64_t)((oc0 + row) * KDIM + seg * 8) * 2;
        bDst[i] = aDst[i];
        bSrc[i] = ((uint64_t)(pix0 + row) * KDIM + seg * 8) * 2;
    }
    const char* whB   = (const char*)g_wh;
    const char* bcolB = (const char*)g_bcol;

    // ---- ldmatrix lane addressing ----
    const uint32_t aOffB = (uint32_t)((wm * 64 + (lane & 15)) * PITCH + (lane >> 4) * 16);
    const int bRow = ((lane >> 4) << 3) | (lane & 7);
    const int bSel = (lane >> 3) & 1;
    const uint32_t bOffB = (uint32_t)((wn * 32 + bRow) * PITCH + bSel * 16);

    float acc[4][4][4];
    #pragma unroll
    for (int i = 0; i < 4; i++)
        #pragma unroll
        for (int j = 0; j < 4; j++)
            #pragma unroll
            for (int q = 0; q < 4; q++)
                acc[i][j][q] = 0.0f;

    // ---- prologue: fill stages 0..2 ----
    #pragma unroll
    for (int s = 0; s < NSTAGE - 1; ++s) {
        const uint32_t st = sb + (uint32_t)(s * STAGE_B);
        const uint64_t kB = (uint64_t)s * BK * 2;
        #pragma unroll
        for (int i = 0; i < 2; ++i) {
            cp16(st + OFF_A + aDst[i], whB + aSrc[i] + kB);
            cp16(st + OFF_B + bDst[i], bcolB + bSrc[i] + kB);
        }
        asm volatile("cp.async.commit_group;" ::: "memory");
    }

    #pragma unroll 1
    for (int chunk = 0; chunk < NCHUNK; ++chunk) {
        asm volatile("cp.async.wait_group %0;" :: "n"(NSTAGE - 2) : "memory");
        __syncthreads();

        // ---- issue chunk+3 into just-freed stage ----
        {
            const int cn = chunk + NSTAGE - 1;
            if (cn < NCHUNK) {
                const uint32_t st = sb + (uint32_t)((cn & 3) * STAGE_B);
                const uint64_t kB = (uint64_t)cn * BK * 2;
                #pragma unroll
                for (int i = 0; i < 2; ++i) {
                    cp16(st + OFF_A + aDst[i], whB + aSrc[i] + kB);
                    cp16(st + OFF_B + bDst[i], bcolB + bSrc[i] + kB);
                }
            }
            asm volatile("cp.async.commit_group;" ::: "memory");
        }

        // ---- MMA from stage chunk%4: 2 k16 steps x (4M x 4N tiles) ----
        const uint32_t bufS = sb + (uint32_t)((chunk & 3) * STAGE_B);
        #pragma unroll
        for (int ks = 0; ks < 2; ++ks) {
            const uint32_t ko = (uint32_t)(ks * 32);
            uint32_t bf[8];
            #pragma unroll
            for (int nb = 0; nb < 2; ++nb)
                ldsm4(&bf[nb * 4], bufS + OFF_B + bOffB + ko + (uint32_t)(nb * 16 * PITCH));
            uint32_t af[16];
            #pragma unroll
            for (int mt = 0; mt < 4; ++mt)
                ldsm4(&af[mt * 4], bufS + OFF_A + aOffB + ko + (uint32_t)(mt * 16 * PITCH));
            #pragma unroll
            for (int mt = 0; mt < 4; ++mt)
                #pragma unroll
                for (int nt = 0; nt < 4; ++nt)
                    mma16816(acc[mt][nt], &af[mt * 4], bf[nt * 2], bf[nt * 2 + 1]);
        }
    }

    // ---- epilogue ----
    #pragma unroll
    for (int mt = 0; mt < 4; ++mt) {
        const int r0 = oc0 + wm * 64 + mt * 16 + (lane >> 2);
        const int r1 = r0 + 8;
        const float bv0 = __ldg(&bias[r0]);
        const float bv1 = __ldg(&bias[r1]);
        #pragma unroll
        for (int nt = 0; nt < 4; ++nt) {
            const int pg   = pix0 + wn * 32 + nt * 8 + (lane & 3) * 2;
            const int nimg = pg / HWI;
            const int hw   = pg - nimg * HWI;
            const float* c = acc[mt][nt];
            float2 v0 = make_float2(c[0] + bv0, c[1] + bv0);
            float2 v1 = make_float2(c[2] + bv1, c[3] + bv1);
            *(float2*)&out[((size_t)nimg * 256 + r0) * HWI + hw] = v0;
            *(float2*)&out[((size_t)nimg * 256 + r1) * HWI + hw] = v1;
        }
    }
}

extern "C" void kernel_launch(void* const* d_in, const int* in_sizes, int n_in,
                              void* d_out, int out_size)
{
    const float* x    = (const float*)d_in[0];   // [32,128,56,56]
    const float* wgt  = (const float*)d_in[1];   // [256,128,3,3]
    const float* bias = (const float*)d_in[2];   // [256]
    float* out        = (float*)d_out;           // [32,256,56,56]

    cudaFuncSetAttribute(conv_main,
                         cudaFuncAttributeMaxDynamicSharedMemorySize, SMEM_TOTAL);

    prep_w<<<144, 256>>>(wgt);
    prep_im2col<<<(NPIX * (KDIM / 8) + 255) / 256, 256>>>(x);
    dim3 grid(2, NPIX / 128);                    // oc fast -> L2 reuse of B
    conv_main<<<grid, 256, SMEM_TOTAL>>>(bias, out);
}

// round 10
// speedup vs baseline: 6.4747x; 1.7337x over previous
#include <cuda_runtime.h>
#include <cuda_fp16.h>
#include <cstdint>

// Conv as implicit GEMM, single-pass fp16 (fp32 acc), tap-decomposed K.
// K order: k = (r*3+s)*128 + c  ->  every BK=32 chunk sits inside one tap, so
// the B tile is x itself (fp16 NHWC) at a shifted pixel; padding via cp.async zfill.
// No im2col matrix. Pre-kernels: w -> fp16 [oc][tap*128+c]; x -> fp16 NHWC (51MB, L2-resident).
// Main: 4-stage cp.async ring + ldmatrix + mma.sync m16n8k16.
// CTA 128(oc) x 128(pix), 8 warps (2M x 4N), warp tile 64x32, 2 CTAs/SM.

#define C_IN   128
#define HWI    3136
#define NPIX   100352
#define KDIM   1152
#define BK     32
#define NCHUNK 36
#define PITCH  80         // smem row pitch bytes (64B data + 16 pad)

#define OFF_A   0
#define OFF_B   10240     // 128*80
#define STAGE_B 20480
#define NSTAGE  4
#define SMEM_TOTAL (NSTAGE * STAGE_B)   // 81920

__device__ __align__(16) __half g_wh[256 * KDIM];                 // [oc][tap*128+c]
__device__ __align__(16) __half g_xh[(size_t)32 * HWI * C_IN];    // NHWC fp16, 51MB

static __device__ __forceinline__ uint32_t s2u(const void* p) {
    uint32_t a;
    asm("{ .reg .u64 t; cvta.to.shared.u64 t, %1; cvt.u32.u64 %0, t; }" : "=r"(a) : "l"(p));
    return a;
}

static __device__ __forceinline__ void cp16(uint32_t dst, const void* src) {
    asm volatile("cp.async.cg.shared.global [%0], [%1], 16;" :: "r"(dst), "l"(src));
}

// zfill form: copies src_sz bytes (0 or 16), zero-fills the rest of 16
static __device__ __forceinline__ void cp16z(uint32_t dst, const void* src, uint32_t src_sz) {
    asm volatile("cp.async.cg.shared.global [%0], [%1], 16, %2;"
                 :: "r"(dst), "l"(src), "r"(src_sz));
}

static __device__ __forceinline__ void ldsm4(uint32_t* r, uint32_t addr) {
    asm volatile("ldmatrix.sync.aligned.m8n8.x4.shared.b16 {%0,%1,%2,%3}, [%4];"
                 : "=r"(r[0]), "=r"(r[1]), "=r"(r[2]), "=r"(r[3]) : "r"(addr));
}

static __device__ __forceinline__ void mma16816(float* c, const uint32_t* a,
                                                uint32_t b0, uint32_t b1) {
    asm volatile(
        "mma.sync.aligned.m16n8k16.row.col.f32.f16.f16.f32 "
        "{%0,%1,%2,%3}, {%4,%5,%6,%7}, {%8,%9}, {%0,%1,%2,%3};"
        : "+f"(c[0]), "+f"(c[1]), "+f"(c[2]), "+f"(c[3])
        : "r"(a[0]), "r"(a[1]), "r"(a[2]), "r"(a[3]), "r"(b0), "r"(b1));
}

// ---------- pre-kernel 1: weights fp32 -> fp16, reordered to k=(tap)*128+c ----------
__global__ void prep_w(const float* __restrict__ w) {
    const int gid = blockIdx.x * 256 + threadIdx.x;   // 36864 = 256 oc x 144 segs
    const int oc = gid / 144;
    const int j  = gid - oc * 144;                    // 8 new-k elems, same tap
    const int tap = j >> 4;                           // j*8/128
    const int c0  = (j & 15) * 8;
    __half h[8];
    #pragma unroll
    for (int e = 0; e < 8; ++e)
        h[e] = __float2half_rn(w[oc * KDIM + (c0 + e) * 9 + tap]);
    *(uint4*)&g_wh[oc * KDIM + j * 8] = *(uint4*)h;
}

// ---------- pre-kernel 2: x fp32 NCHW -> fp16 NHWC (smem transpose) ----------
// smem pitch 136 halfs = 272 B = 17*16: 16B-aligned uint4 reads at part*32 offsets.
__global__ void prep_nhwc(const float* __restrict__ x) {
    __shared__ __half sm[64][136];
    const int hw0 = blockIdx.x * 64;
    const int n   = blockIdx.y;
    const int tid = threadIdx.x;
    const int c4  = tid >> 6;                         // 0..3
    const int hwi = tid & 63;
    const float* __restrict__ xn = x + (size_t)n * C_IN * HWI;
    #pragma unroll
    for (int cc = 0; cc < 32; ++cc) {
        const int c = c4 * 32 + cc;
        sm[hwi][c] = __float2half_rn(xn[(size_t)c * HWI + hw0 + hwi]);
    }
    __syncthreads();
    const int row  = tid >> 2;
    const int part = tid & 3;
    __half* dst = &g_xh[((size_t)(n * HWI + hw0 + row)) * C_IN + part * 32];
    const __half* srcp = &sm[row][part * 32];
    #pragma unroll
    for (int q = 0; q < 4; ++q)
        *(uint4*)(dst + q * 8) = *(const uint4*)(srcp + q * 8);
}

// ---------- main GEMM kernel ----------
__global__ __launch_bounds__(256, 2)
void conv_main(const float* __restrict__ bias, float* __restrict__ out)
{
    extern __shared__ __align__(16) char smem[];
    const uint32_t sb = s2u(smem);

    const int tid  = threadIdx.x;
    const int lane = tid & 31;
    const int wid  = tid >> 5;
    const int oc0  = blockIdx.x * 128;
    const int pix0 = blockIdx.y * 128;

    const int wm = wid & 1;       // M: 2 x 64
    const int wn = wid >> 1;      // N: 4 x 32

    // ---- chore precompute: A 512 x 16B, B 512 x 16B (2 each per thread) ----
    uint32_t aDst[2];
    uint64_t aSrc[2];
    const char* bBase[2];         // &g_xh[n*HWI*128 + seg*8] in bytes
    int bOh[2], bOw[2];
    #pragma unroll
    for (int i = 0; i < 2; ++i) {
        const int ch = tid + 256 * i;
        const int row = ch >> 2, seg = ch & 3;
        aDst[i] = (uint32_t)(row * PITCH + seg * 16);
        aSrc[i] = (uint64_t)((oc0 + row) * KDIM + seg * 8) * 2;
        const int pg = pix0 + row;
        const int n  = pg / HWI;
        const int hw = pg - n * HWI;
        bOh[i] = hw / 56;
        bOw[i] = hw - bOh[i] * 56;
        bBase[i] = (const char*)g_xh + ((size_t)n * HWI * C_IN + seg * 8) * 2;
    }
    const char* whB = (const char*)g_wh;

    // ---- ldmatrix lane addressing ----
    const uint32_t aOffB = (uint32_t)((wm * 64 + (lane & 15)) * PITCH + (lane >> 4) * 16);
    const int bRow = ((lane >> 4) << 3) | (lane & 7);
    const int bSel = (lane >> 3) & 1;
    const uint32_t bOffB = (uint32_t)((wn * 32 + bRow) * PITCH + bSel * 16);

    float acc[4][4][4];
    #pragma unroll
    for (int i = 0; i < 4; i++)
        #pragma unroll
        for (int j = 0; j < 4; j++)
            #pragma unroll
            for (int q = 0; q < 4; q++)
                acc[i][j][q] = 0.0f;

    // ---- fill helper: proper scoping via lambda (the R9 macro shadowed its
    //      caller's loop variable, corrupting prologue chunks 0-2) ----
    auto fill_stage = [&](int ck, uint32_t st) {
        const int tp  = ck >> 2;
        const int fr  = (tp * 11) >> 5;           // tp/3 for tp<9
        const int fs  = tp - fr * 3;
        const int fc0 = (ck & 3) * 32;
        const uint64_t kB = (uint64_t)ck * BK * 2;
        #pragma unroll
        for (int i = 0; i < 2; ++i) {
            cp16(st + OFF_A + aDst[i], whB + aSrc[i] + kB);
            const int ih = bOh[i] + fr - 1;
            const int iw = bOw[i] + fs - 1;
            const uint32_t ok = ((unsigned)ih < 56u && (unsigned)iw < 56u) ? 16u : 0u;
            const char* src = bBase[i] + ((ptrdiff_t)(ih * 56 + iw) * C_IN + fc0) * 2;
            cp16z(st + OFF_B + aDst[i], src, ok);
        }
        asm volatile("cp.async.commit_group;" ::: "memory");
    };

    // ---- prologue: fill stages 0..2 ----
    #pragma unroll
    for (int s = 0; s < NSTAGE - 1; ++s)
        fill_stage(s, sb + (uint32_t)(s * STAGE_B));

    #pragma unroll 1
    for (int chunk = 0; chunk < NCHUNK; ++chunk) {
        asm volatile("cp.async.wait_group %0;" :: "n"(NSTAGE - 2) : "memory");
        __syncthreads();

        // ---- issue chunk+3 into just-freed stage ----
        {
            const int cn = chunk + NSTAGE - 1;
            if (cn < NCHUNK) {
                fill_stage(cn, sb + (uint32_t)((cn & 3) * STAGE_B));
            } else {
                asm volatile("cp.async.commit_group;" ::: "memory");
            }
        }

        // ---- MMA from stage chunk%4: 2 k16 steps x (4M x 4N tiles) ----
        const uint32_t bufS = sb + (uint32_t)((chunk & 3) * STAGE_B);
        #pragma unroll
        for (int ks = 0; ks < 2; ++ks) {
            const uint32_t ko = (uint32_t)(ks * 32);
            uint32_t bf[8];
            #pragma unroll
            for (int nb = 0; nb < 2; ++nb)
                ldsm4(&bf[nb * 4], bufS + OFF_B + bOffB + ko + (uint32_t)(nb * 16 * PITCH));
            uint32_t af[16];
            #pragma unroll
            for (int mt = 0; mt < 4; ++mt)
                ldsm4(&af[mt * 4], bufS + OFF_A + aOffB + ko + (uint32_t)(mt * 16 * PITCH));
            #pragma unroll
            for (int mt = 0; mt < 4; ++mt)
                #pragma unroll
                for (int nt = 0; nt < 4; ++nt)
                    mma16816(acc[mt][nt], &af[mt * 4], bf[nt * 2], bf[nt * 2 + 1]);
        }
    }

    // ---- epilogue ----
    #pragma unroll
    for (int mt = 0; mt < 4; ++mt) {
        const int r0 = oc0 + wm * 64 + mt * 16 + (lane >> 2);
        const int r1 = r0 + 8;
        const float bv0 = __ldg(&bias[r0]);
        const float bv1 = __ldg(&bias[r1]);
        #pragma unroll
        for (int nt = 0; nt < 4; ++nt) {
            const int pg   = pix0 + wn * 32 + nt * 8 + (lane & 3) * 2;
            const int nimg = pg / HWI;
            const int hw   = pg - nimg * HWI;
            const float* c = acc[mt][nt];
            float2 v0 = make_float2(c[0] + bv0, c[1] + bv0);
            float2 v1 = make_float2(c[2] + bv1, c[3] + bv1);
            *(float2*)&out[((size_t)nimg * 256 + r0) * HWI + hw] = v0;
            *(float2*)&out[((size_t)nimg * 256 + r1) * HWI + hw] = v1;
        }
    }
}

extern "C" void kernel_launch(void* const* d_in, const int* in_sizes, int n_in,
                              void* d_out, int out_size)
{
    const float* x    = (const float*)d_in[0];   // [32,128,56,56]
    const float* wgt  = (const float*)d_in[1];   // [256,128,3,3]
    const float* bias = (const float*)d_in[2];   // [256]
    float* out        = (float*)d_out;           // [32,256,56,56]

    cudaFuncSetAttribute(conv_main,
                         cudaFuncAttributeMaxDynamicSharedMemorySize, SMEM_TOTAL);

    prep_w<<<144, 256>>>(wgt);
    prep_nhwc<<<dim3(HWI / 64, 32), 256>>>(x);
    dim3 grid(2, NPIX / 128);                    // oc fast -> L2 reuse of B
    conv_main<<<grid, 256, SMEM_TOTAL>>>(bias, out);
}

// round 11
// speedup vs baseline: 7.1026x; 1.0970x over previous
#include <cuda_runtime.h>
#include <cuda_fp16.h>
#include <cstdint>

// Conv as implicit GEMM, single-pass fp16 (fp32 acc), tap-decomposed K.
// K order: k = (r*3+s)*128 + c. BK=64 = half a tap -> 18 chunks, 3-stage
// cp.async ring (1-chunk prefetch distance), 2 CTAs/SM.
// CTA 128(oc) x 128(pix), 8 warps (2M x 4N), warp tile 64x32.

#define C_IN   128
#define HWI    3136
#define NPIX   100352
#define KDIM   1152
#define BK     64
#define NCHUNK 18
#define PITCH  144        // smem row pitch bytes (128B data + 16 pad)

#define OFF_A   0
#define OFF_B   18432     // 128*144
#define STAGE_B 36864
#define NSTAGE  3
#define SMEM_TOTAL (NSTAGE * STAGE_B)   // 110592

__device__ __align__(16) __half g_wh[256 * KDIM];                 // [oc][tap*128+c]
__device__ __align__(16) __half g_xh[(size_t)32 * HWI * C_IN];    // NHWC fp16, 51MB

static __device__ __forceinline__ uint32_t s2u(const void* p) {
    uint32_t a;
    asm("{ .reg .u64 t; cvta.to.shared.u64 t, %1; cvt.u32.u64 %0, t; }" : "=r"(a) : "l"(p));
    return a;
}

static __device__ __forceinline__ void cp16(uint32_t dst, const void* src) {
    asm volatile("cp.async.cg.shared.global [%0], [%1], 16;" :: "r"(dst), "l"(src));
}

// zfill form: copies src_sz bytes (0 or 16), zero-fills the rest of 16
static __device__ __forceinline__ void cp16z(uint32_t dst, const void* src, uint32_t src_sz) {
    asm volatile("cp.async.cg.shared.global [%0], [%1], 16, %2;"
                 :: "r"(dst), "l"(src), "r"(src_sz));
}

static __device__ __forceinline__ void ldsm4(uint32_t* r, uint32_t addr) {
    asm volatile("ldmatrix.sync.aligned.m8n8.x4.shared.b16 {%0,%1,%2,%3}, [%4];"
                 : "=r"(r[0]), "=r"(r[1]), "=r"(r[2]), "=r"(r[3]) : "r"(addr));
}

static __device__ __forceinline__ void mma16816(float* c, const uint32_t* a,
                                                uint32_t b0, uint32_t b1) {
    asm volatile(
        "mma.sync.aligned.m16n8k16.row.col.f32.f16.f16.f32 "
        "{%0,%1,%2,%3}, {%4,%5,%6,%7}, {%8,%9}, {%0,%1,%2,%3};"
        : "+f"(c[0]), "+f"(c[1]), "+f"(c[2]), "+f"(c[3])
        : "r"(a[0]), "r"(a[1]), "r"(a[2]), "r"(a[3]), "r"(b0), "r"(b1));
}

// ---------- pre-kernel 1: weights fp32 -> fp16, reordered to k=(tap)*128+c ----------
__global__ void prep_w(const float* __restrict__ w) {
    const int gid = blockIdx.x * 256 + threadIdx.x;   // 36864 = 256 oc x 144 segs
    const int oc = gid / 144;
    const int j  = gid - oc * 144;                    // 8 new-k elems, same tap
    const int tap = j >> 4;
    const int c0  = (j & 15) * 8;
    __half h[8];
    #pragma unroll
    for (int e = 0; e < 8; ++e)
        h[e] = __float2half_rn(w[oc * KDIM + (c0 + e) * 9 + tap]);
    *(uint4*)&g_wh[oc * KDIM + j * 8] = *(uint4*)h;
}

// ---------- pre-kernel 2: x fp32 NCHW -> fp16 NHWC (smem transpose) ----------
__global__ void prep_nhwc(const float* __restrict__ x) {
    __shared__ __half sm[64][136];                    // 272B pitch: 16B-aligned reads
    const int hw0 = blockIdx.x * 64;
    const int n   = blockIdx.y;
    const int tid = threadIdx.x;
    const int c4  = tid >> 6;
    const int hwi = tid & 63;
    const float* __restrict__ xn = x + (size_t)n * C_IN * HWI;
    #pragma unroll
    for (int cc = 0; cc < 32; ++cc) {
        const int c = c4 * 32 + cc;
        sm[hwi][c] = __float2half_rn(xn[(size_t)c * HWI + hw0 + hwi]);
    }
    __syncthreads();
    const int row  = tid >> 2;
    const int part = tid & 3;
    __half* dst = &g_xh[((size_t)(n * HWI + hw0 + row)) * C_IN + part * 32];
    const __half* srcp = &sm[row][part * 32];
    #pragma unroll
    for (int q = 0; q < 4; ++q)
        *(uint4*)(dst + q * 8) = *(const uint4*)(srcp + q * 8);
}

// ---------- main GEMM kernel ----------
__global__ __launch_bounds__(256, 2)
void conv_main(const float* __restrict__ bias, float* __restrict__ out)
{
    extern __shared__ __align__(16) char smem[];
    const uint32_t sb = s2u(smem);

    const int tid  = threadIdx.x;
    const int lane = tid & 31;
    const int wid  = tid >> 5;
    const int oc0  = blockIdx.x * 128;
    const int pix0 = blockIdx.y * 128;

    const int wm = wid & 1;       // M: 2 x 64
    const int wn = wid >> 1;      // N: 4 x 32

    // ---- chore precompute: A 1024 x 16B, B 1024 x 16B (4 each per thread) ----
    // chore ch = tid + 256*i : row = ch>>3 (0..127), seg = ch&7 (16B within 128B row)
    uint32_t dDst[4];
    uint64_t aSrc[4];
    const char* bBase[4];
    int bOh[4], bOw[4];
    #pragma unroll
    for (int i = 0; i < 4; ++i) {
        const int ch  = tid + 256 * i;
        const int row = ch >> 3, seg = ch & 7;
        dDst[i] = (uint32_t)(row * PITCH + seg * 16);
        aSrc[i] = (uint64_t)((oc0 + row) * KDIM + seg * 8) * 2;
        const int pg = pix0 + row;
        const int n  = pg / HWI;
        const int hw = pg - n * HWI;
        bOh[i] = hw / 56;
        bOw[i] = hw - bOh[i] * 56;
        bBase[i] = (const char*)g_xh + ((size_t)n * HWI * C_IN + seg * 8) * 2;
    }
    const char* whB = (const char*)g_wh;

    // ---- ldmatrix lane addressing ----
    const uint32_t aOffB = (uint32_t)((wm * 64 + (lane & 15)) * PITCH + (lane >> 4) * 16);
    const int bRow = ((lane >> 4) << 3) | (lane & 7);
    const int bSel = (lane >> 3) & 1;
    const uint32_t bOffB = (uint32_t)((wn * 32 + bRow) * PITCH + bSel * 16);

    float acc[4][4][4];
    #pragma unroll
    for (int i = 0; i < 4; i++)
        #pragma unroll
        for (int j = 0; j < 4; j++)
            #pragma unroll
            for (int q = 0; q < 4; q++)
                acc[i][j][q] = 0.0f;

    // ---- fill one stage with chunk ck (BK=64 = half tap) ----
    auto fill_stage = [&](int ck, uint32_t st) {
        const int tp  = ck >> 1;
        const int fr  = (tp * 11) >> 5;           // tp/3 for tp<9
        const int fs  = tp - fr * 3;
        const int fc0 = (ck & 1) * 64;
        const uint64_t kB = (uint64_t)ck * BK * 2;
        #pragma unroll
        for (int i = 0; i < 4; ++i) {
            cp16(st + OFF_A + dDst[i], whB + aSrc[i] + kB);
            const int ih = bOh[i] + fr - 1;
            const int iw = bOw[i] + fs - 1;
            const uint32_t ok = ((unsigned)ih < 56u && (unsigned)iw < 56u) ? 16u : 0u;
            const char* src = bBase[i] + ((ptrdiff_t)(ih * 56 + iw) * C_IN + fc0) * 2;
            cp16z(st + OFF_B + dDst[i], src, ok);
        }
        asm volatile("cp.async.commit_group;" ::: "memory");
    };

    // stage index table: stage of chunk ck = ck % 3
    auto stage_of = [&](int ck) { return sb + (uint32_t)((ck % 3) * STAGE_B); };

    // ---- prologue: fill stages for chunks 0,1 ----
    fill_stage(0, stage_of(0));
    fill_stage(1, stage_of(1));

    #pragma unroll 1
    for (int chunk = 0; chunk < NCHUNK; ++chunk) {
        asm volatile("cp.async.wait_group %0;" :: "n"(NSTAGE - 2) : "memory");
        __syncthreads();

        // ---- issue chunk+2 into just-freed stage ----
        {
            const int cn = chunk + NSTAGE - 1;
            if (cn < NCHUNK) {
                fill_stage(cn, stage_of(cn));
            } else {
                asm volatile("cp.async.commit_group;" ::: "memory");
            }
        }

        // ---- MMA from stage chunk%3: 4 k16 steps x (4M x 4N tiles) ----
        const uint32_t bufS = stage_of(chunk);
        #pragma unroll
        for (int ks = 0; ks < 4; ++ks) {
            const uint32_t ko = (uint32_t)(ks * 32);
            uint32_t bf[8];
            #pragma unroll
            for (int nb = 0; nb < 2; ++nb)
                ldsm4(&bf[nb * 4], bufS + OFF_B + bOffB + ko + (uint32_t)(nb * 16 * PITCH));
            uint32_t af[16];
            #pragma unroll
            for (int mt = 0; mt < 4; ++mt)
                ldsm4(&af[mt * 4], bufS + OFF_A + aOffB + ko + (uint32_t)(mt * 16 * PITCH));
            #pragma unroll
            for (int mt = 0; mt < 4; ++mt)
                #pragma unroll
                for (int nt = 0; nt < 4; ++nt)
                    mma16816(acc[mt][nt], &af[mt * 4], bf[nt * 2], bf[nt * 2 + 1]);
        }
    }

    // ---- epilogue ----
    #pragma unroll
    for (int mt = 0; mt < 4; ++mt) {
        const int r0 = oc0 + wm * 64 + mt * 16 + (lane >> 2);
        const int r1 = r0 + 8;
        const float bv0 = __ldg(&bias[r0]);
        const float bv1 = __ldg(&bias[r1]);
        #pragma unroll
        for (int nt = 0; nt < 4; ++nt) {
            const int pg   = pix0 + wn * 32 + nt * 8 + (lane & 3) * 2;
            const int nimg = pg / HWI;
            const int hw   = pg - nimg * HWI;
            const float* c = acc[mt][nt];
            float2 v0 = make_float2(c[0] + bv0, c[1] + bv0);
            float2 v1 = make_float2(c[2] + bv1, c[3] + bv1);
            *(float2*)&out[((size_t)nimg * 256 + r0) * HWI + hw] = v0;
            *(float2*)&out[((size_t)nimg * 256 + r1) * HWI + hw] = v1;
        }
    }
}

extern "C" void kernel_launch(void* const* d_in, const int* in_sizes, int n_in,
                              void* d_out, int out_size)
{
    const float* x    = (const float*)d_in[0];   // [32,128,56,56]
    const float* wgt  = (const float*)d_in[1];   // [256,128,3,3]
    const float* bias = (const float*)d_in[2];   // [256]
    float* out        = (float*)d_out;           // [32,256,56,56]

    cudaFuncSetAttribute(conv_main,
                         cudaFuncAttributeMaxDynamicSharedMemorySize, SMEM_TOTAL);

    prep_w<<<144, 256>>>(wgt);
    prep_nhwc<<<dim3(HWI / 64, 32), 256>>>(x);
    dim3 grid(2, NPIX / 128);                    // oc fast -> L2 reuse of B
    conv_main<<<grid, 256, SMEM_TOTAL>>>(bias, out);
}

// round 12
// speedup vs baseline: 7.1048x; 1.0003x over previous
#include <cuda_runtime.h>
#include <cuda_fp16.h>
#include <cstdint>

// Conv as implicit GEMM, single-pass fp16 (fp32 acc), tap-decomposed K.
// K order: k = (r*3+s)*128 + c. BK=64 = half a tap -> 18 chunks, 3-stage
// cp.async ring, 2 CTAs/SM. Fragment ping-pong: every ldmatrix issues under
// MMA cover of the previous fragment.
// CTA 128(oc) x 128(pix), 8 warps (2M x 4N), warp tile 64x32.

#define C_IN   128
#define HWI    3136
#define NPIX   100352
#define KDIM   1152
#define BK     64
#define NCHUNK 18
#define PITCH  144        // smem row pitch bytes (128B data + 16 pad)

#define OFF_A   0
#define OFF_B   18432     // 128*144
#define STAGE_B 36864
#define NSTAGE  3
#define SMEM_TOTAL (NSTAGE * STAGE_B)   // 110592

__device__ __align__(16) __half g_wh[256 * KDIM];                 // [oc][tap*128+c]
__device__ __align__(16) __half g_xh[(size_t)32 * HWI * C_IN];    // NHWC fp16, 51MB

static __device__ __forceinline__ uint32_t s2u(const void* p) {
    uint32_t a;
    asm("{ .reg .u64 t; cvta.to.shared.u64 t, %1; cvt.u32.u64 %0, t; }" : "=r"(a) : "l"(p));
    return a;
}

static __device__ __forceinline__ void cp16(uint32_t dst, const void* src) {
    asm volatile("cp.async.cg.shared.global [%0], [%1], 16;" :: "r"(dst), "l"(src));
}

static __device__ __forceinline__ void cp16z(uint32_t dst, const void* src, uint32_t src_sz) {
    asm volatile("cp.async.cg.shared.global [%0], [%1], 16, %2;"
                 :: "r"(dst), "l"(src), "r"(src_sz));
}

static __device__ __forceinline__ void ldsm4(uint32_t* r, uint32_t addr) {
    asm volatile("ldmatrix.sync.aligned.m8n8.x4.shared.b16 {%0,%1,%2,%3}, [%4];"
                 : "=r"(r[0]), "=r"(r[1]), "=r"(r[2]), "=r"(r[3]) : "r"(addr));
}

static __device__ __forceinline__ void mma16816(float* c, const uint32_t* a,
                                                uint32_t b0, uint32_t b1) {
    asm volatile(
        "mma.sync.aligned.m16n8k16.row.col.f32.f16.f16.f32 "
        "{%0,%1,%2,%3}, {%4,%5,%6,%7}, {%8,%9}, {%0,%1,%2,%3};"
        : "+f"(c[0]), "+f"(c[1]), "+f"(c[2]), "+f"(c[3])
        : "r"(a[0]), "r"(a[1]), "r"(a[2]), "r"(a[3]), "r"(b0), "r"(b1));
}

// ---------- pre-kernel 1: weights fp32 -> fp16, reordered to k=(tap)*128+c ----------
__global__ void prep_w(const float* __restrict__ w) {
    const int gid = blockIdx.x * 256 + threadIdx.x;   // 36864 = 256 oc x 144 segs
    const int oc = gid / 144;
    const int j  = gid - oc * 144;
    const int tap = j >> 4;
    const int c0  = (j & 15) * 8;
    __half h[8];
    #pragma unroll
    for (int e = 0; e < 8; ++e)
        h[e] = __float2half_rn(w[oc * KDIM + (c0 + e) * 9 + tap]);
    *(uint4*)&g_wh[oc * KDIM + j * 8] = *(uint4*)h;
}

// ---------- pre-kernel 2: x fp32 NCHW -> fp16 NHWC (smem transpose) ----------
__global__ void prep_nhwc(const float* __restrict__ x) {
    __shared__ __half sm[64][136];                    // 272B pitch: 16B-aligned reads
    const int hw0 = blockIdx.x * 64;
    const int n   = blockIdx.y;
    const int tid = threadIdx.x;
    const int c4  = tid >> 6;
    const int hwi = tid & 63;
    const float* __restrict__ xn = x + (size_t)n * C_IN * HWI;
    #pragma unroll
    for (int cc = 0; cc < 32; ++cc) {
        const int c = c4 * 32 + cc;
        sm[hwi][c] = __float2half_rn(xn[(size_t)c * HWI + hw0 + hwi]);
    }
    __syncthreads();
    const int row  = tid >> 2;
    const int part = tid & 3;
    __half* dst = &g_xh[((size_t)(n * HWI + hw0 + row)) * C_IN + part * 32];
    const __half* srcp = &sm[row][part * 32];
    #pragma unroll
    for (int q = 0; q < 4; ++q)
        *(uint4*)(dst + q * 8) = *(const uint4*)(srcp + q * 8);
}

// ---------- main GEMM kernel ----------
__global__ __launch_bounds__(256, 2)
void conv_main(const float* __restrict__ bias, float* __restrict__ out)
{
    extern __shared__ __align__(16) char smem[];
    const uint32_t sb = s2u(smem);

    const int tid  = threadIdx.x;
    const int lane = tid & 31;
    const int wid  = tid >> 5;
    const int oc0  = blockIdx.x * 128;
    const int pix0 = blockIdx.y * 128;

    const int wm = wid & 1;       // M: 2 x 64
    const int wn = wid >> 1;      // N: 4 x 32

    // ---- chore precompute: A 1024 x 16B, B 1024 x 16B (4 each per thread) ----
    uint32_t dDst[4];
    uint64_t aSrc[4];
    const char* bBase[4];
    int bOh[4], bOw[4];
    #pragma unroll
    for (int i = 0; i < 4; ++i) {
        const int ch  = tid + 256 * i;
        const int row = ch >> 3, seg = ch & 7;
        dDst[i] = (uint32_t)(row * PITCH + seg * 16);
        aSrc[i] = (uint64_t)((oc0 + row) * KDIM + seg * 8) * 2;
        const int pg = pix0 + row;
        const int n  = pg / HWI;
        const int hw = pg - n * HWI;
        bOh[i] = hw / 56;
        bOw[i] = hw - bOh[i] * 56;
        bBase[i] = (const char*)g_xh + ((size_t)n * HWI * C_IN + seg * 8) * 2;
    }
    const char* whB = (const char*)g_wh;

    // ---- ldmatrix lane addressing ----
    const uint32_t aOffB = (uint32_t)((wm * 64 + (lane & 15)) * PITCH + (lane >> 4) * 16);
    const int bRow = ((lane >> 4) << 3) | (lane & 7);
    const int bSel = (lane >> 3) & 1;
    const uint32_t bOffB = (uint32_t)((wn * 32 + bRow) * PITCH + bSel * 16);

    float acc[4][4][4];
    #pragma unroll
    for (int i = 0; i < 4; i++)
        #pragma unroll
        for (int j = 0; j < 4; j++)
            #pragma unroll
            for (int q = 0; q < 4; q++)
                acc[i][j][q] = 0.0f;

    // ---- fill one stage with chunk ck (BK=64 = half tap) ----
    auto fill_stage = [&](int ck, uint32_t st) {
        const int tp  = ck >> 1;
        const int fr  = (tp * 11) >> 5;           // tp/3 for tp<9
        const int fs  = tp - fr * 3;
        const int fc0 = (ck & 1) * 64;
        const uint64_t kB = (uint64_t)ck * BK * 2;
        #pragma unroll
        for (int i = 0; i < 4; ++i) {
            cp16(st + OFF_A + dDst[i], whB + aSrc[i] + kB);
            const int ih = bOh[i] + fr - 1;
            const int iw = bOw[i] + fs - 1;
            const uint32_t ok = ((unsigned)ih < 56u && (unsigned)iw < 56u) ? 16u : 0u;
            const char* src = bBase[i] + ((ptrdiff_t)(ih * 56 + iw) * C_IN + fc0) * 2;
            cp16z(st + OFF_B + dDst[i], src, ok);
        }
        asm volatile("cp.async.commit_group;" ::: "memory");
    };

    auto stage_of = [&](int ck) { return sb + (uint32_t)((ck % 3) * STAGE_B); };

    // ---- prologue: fill stages for chunks 0,1 ----
    fill_stage(0, stage_of(0));
    fill_stage(1, stage_of(1));

    #pragma unroll 1
    for (int chunk = 0; chunk < NCHUNK; ++chunk) {
        asm volatile("cp.async.wait_group %0;" :: "n"(NSTAGE - 2) : "memory");
        __syncthreads();

        // ---- issue chunk+2 into just-freed stage ----
        {
            const int cn = chunk + NSTAGE - 1;
            if (cn < NCHUNK) {
                fill_stage(cn, stage_of(cn));
            } else {
                asm volatile("cp.async.commit_group;" ::: "memory");
            }
        }

        // ---- MMA with ping-pong fragments: ldsm always under MMA cover ----
        const uint32_t bufS = stage_of(chunk);
        const uint32_t aB = bufS + OFF_A + aOffB;
        const uint32_t bB = bufS + OFF_B + bOffB;

        uint32_t bf0[8], bf1[8], af0[4], af1[4];
        // preload ks=0: B fragments + A tile 0
        ldsm4(&bf0[0], bB);
        ldsm4(&bf0[4], bB + 16 * PITCH);
        ldsm4(af0, aB);

        #pragma unroll
        for (int ks = 0; ks < 4; ++ks) {
            uint32_t* bf  = (ks & 1) ? bf1 : bf0;
            uint32_t* bfn = (ks & 1) ? bf0 : bf1;
            const uint32_t ko  = (uint32_t)(ks * 32);
            const uint32_t kon = ko + 32;
            #pragma unroll
            for (int mt = 0; mt < 4; ++mt) {
                uint32_t* afc = (mt & 1) ? af1 : af0;
                uint32_t* afn = (mt & 1) ? af0 : af1;
                if (mt < 3) {
                    ldsm4(afn, aB + ko + (uint32_t)((mt + 1) * 16 * PITCH));
                } else if (ks < 3) {
                    ldsm4(&bfn[0], bB + kon);
                    ldsm4(&bfn[4], bB + kon + 16 * PITCH);
                    ldsm4(afn, aB + kon);
                }
                mma16816(acc[mt][0], afc, bf[0], bf[1]);
                mma16816(acc[mt][1], afc, bf[2], bf[3]);
                mma16816(acc[mt][2], afc, bf[4], bf[5]);
                mma16816(acc[mt][3], afc, bf[6], bf[7]);
            }
        }
    }

    // ---- epilogue ----
    #pragma unroll
    for (int mt = 0; mt < 4; ++mt) {
        const int r0 = oc0 + wm * 64 + mt * 16 + (lane >> 2);
        const int r1 = r0 + 8;
        const float bv0 = __ldg(&bias[r0]);
        const float bv1 = __ldg(&bias[r1]);
        #pragma unroll
        for (int nt = 0; nt < 4; ++nt) {
            const int pg   = pix0 + wn * 32 + nt * 8 + (lane & 3) * 2;
            const int nimg = pg / HWI;
            const int hw   = pg - nimg * HWI;
            const float* c = acc[mt][nt];
            float2 v0 = make_float2(c[0] + bv0, c[1] + bv0);
            float2 v1 = make_float2(c[2] + bv1, c[3] + bv1);
            *(float2*)&out[((size_t)nimg * 256 + r0) * HWI + hw] = v0;
            *(float2*)&out[((size_t)nimg * 256 + r1) * HWI + hw] = v1;
        }
    }
}

extern "C" void kernel_launch(void* const* d_in, const int* in_sizes, int n_in,
                              void* d_out, int out_size)
{
    const float* x    = (const float*)d_in[0];   // [32,128,56,56]
    const float* wgt  = (const float*)d_in[1];   // [256,128,3,3]
    const float* bias = (const float*)d_in[2];   // [256]
    float* out        = (float*)d_out;           // [32,256,56,56]

    cudaFuncSetAttribute(conv_main,
                         cudaFuncAttributeMaxDynamicSharedMemorySize, SMEM_TOTAL);

    prep_w<<<144, 256>>>(wgt);
    prep_nhwc<<<dim3(HWI / 64, 32), 256>>>(x);
    dim3 grid(2, NPIX / 128);                    // oc fast -> L2 reuse of B
    conv_main<<<grid, 256, SMEM_TOTAL>>>(bias, out);
}

// round 14
// speedup vs baseline: 7.2341x; 1.0182x over previous
#include <cuda_runtime.h>
#include <cuda_fp16.h>
#include <cstdint>

// Conv as implicit GEMM, single-pass fp16 (fp32 acc), tap-decomposed K.
// K order: k = (r*3+s)*128 + c. BK=64 = half a tap -> 18 chunks.
// CTA 128(oc) x 64(pix), 128 threads (2Mx2N warps, warp tile 64x32),
// 2-stage cp.async ring, 4 CTAs/SM -> 4 independent barrier domains.

#define C_IN   128
#define HWI    3136
#define NPIX   100352
#define KDIM   1152
#define BK     64
#define NCHUNK 18
#define PITCH  144        // smem row pitch bytes (128B data + 16 pad)

#define OFF_A   0
#define OFF_B   18432     // 128*144
#define STAGE_B 27648     // + 64*144
#define NSTAGE  2
#define SMEM_TOTAL (NSTAGE * STAGE_B)   // 55296

__device__ __align__(16) __half g_wh[256 * KDIM];                 // [oc][tap*128+c]
__device__ __align__(16) __half g_xh[(size_t)32 * HWI * C_IN];    // NHWC fp16, 51MB

static __device__ __forceinline__ uint32_t s2u(const void* p) {
    uint32_t a;
    asm("{ .reg .u64 t; cvta.to.shared.u64 t, %1; cvt.u32.u64 %0, t; }" : "=r"(a) : "l"(p));
    return a;
}

static __device__ __forceinline__ void cp16(uint32_t dst, const void* src) {
    asm volatile("cp.async.cg.shared.global [%0], [%1], 16;" :: "r"(dst), "l"(src));
}

static __device__ __forceinline__ void cp16z(uint32_t dst, const void* src, uint32_t src_sz) {
    asm volatile("cp.async.cg.shared.global [%0], [%1], 16, %2;"
                 :: "r"(dst), "l"(src), "r"(src_sz));
}

static __device__ __forceinline__ void ldsm4(uint32_t* r, uint32_t addr) {
    asm volatile("ldmatrix.sync.aligned.m8n8.x4.shared.b16 {%0,%1,%2,%3}, [%4];"
                 : "=r"(r[0]), "=r"(r[1]), "=r"(r[2]), "=r"(r[3]) : "r"(addr));
}

static __device__ __forceinline__ void mma16816(float* c, const uint32_t* a,
                                                uint32_t b0, uint32_t b1) {
    asm volatile(
        "mma.sync.aligned.m16n8k16.row.col.f32.f16.f16.f32 "
        "{%0,%1,%2,%3}, {%4,%5,%6,%7}, {%8,%9}, {%0,%1,%2,%3};"
        : "+f"(c[0]), "+f"(c[1]), "+f"(c[2]), "+f"(c[3])
        : "r"(a[0]), "r"(a[1]), "r"(a[2]), "r"(a[3]), "r"(b0), "r"(b1));
}

// ---------- pre-kernel 1: weights fp32 -> fp16, reordered to k=(tap)*128+c ----------
__global__ void prep_w(const float* __restrict__ w) {
    const int gid = blockIdx.x * 256 + threadIdx.x;   // 36864 = 256 oc x 144 segs
    const int oc = gid / 144;
    const int j  = gid - oc * 144;
    const int tap = j >> 4;
    const int c0  = (j & 15) * 8;
    __half h[8];
    #pragma unroll
    for (int e = 0; e < 8; ++e)
        h[e] = __float2half_rn(w[oc * KDIM + (c0 + e) * 9 + tap]);
    *(uint4*)&g_wh[oc * KDIM + j * 8] = *(uint4*)h;
}

// ---------- pre-kernel 2: x fp32 NCHW -> fp16 NHWC (smem transpose) ----------
__global__ void prep_nhwc(const float* __restrict__ x) {
    __shared__ __half sm[64][136];                    // 272B pitch: 16B-aligned reads
    const int hw0 = blockIdx.x * 64;
    const int n   = blockIdx.y;
    const int tid = threadIdx.x;
    const int c4  = tid >> 6;
    const int hwi = tid & 63;
    const float* __restrict__ xn = x + (size_t)n * C_IN * HWI;
    #pragma unroll
    for (int cc = 0; cc < 32; ++cc) {
        const int c = c4 * 32 + cc;
        sm[hwi][c] = __float2half_rn(xn[(size_t)c * HWI + hw0 + hwi]);
    }
    __syncthreads();
    const int row  = tid >> 2;
    const int part = tid & 3;
    __half* dst = &g_xh[((size_t)(n * HWI + hw0 + row)) * C_IN + part * 32];
    const __half* srcp = &sm[row][part * 32];
    #pragma unroll
    for (int q = 0; q < 4; ++q)
        *(uint4*)(dst + q * 8) = *(const uint4*)(srcp + q * 8);
}

// ---------- main GEMM kernel ----------
__global__ __launch_bounds__(128, 4)
void conv_main(const float* __restrict__ bias, float* __restrict__ out)
{
    extern __shared__ __align__(16) char smem[];
    const uint32_t sb = s2u(smem);

    const int tid  = threadIdx.x;
    const int lane = tid & 31;
    const int wid  = tid >> 5;
    const int oc0  = blockIdx.x * 128;
    const int pix0 = blockIdx.y * 64;

    const int wm = wid & 1;       // M: 2 x 64
    const int wn = wid >> 1;      // N: 2 x 32

    // ---- fill chores ----
    // A: 8 chores/thread. chore i: row = (tid>>3) + 16*i, seg = tid&7.
    // B: 4 chores/thread, rows row0 + 16*i -> distinct pixels, per-chore base.
    const int rowA = tid >> 3;
    const int segA = tid & 7;
    const uint32_t aDst0 = (uint32_t)(rowA * PITCH + segA * 16);
    const char* aSrc0 = (const char*)g_wh + ((size_t)(oc0 + rowA) * KDIM + segA * 8) * 2;

    uint32_t bDst[4];
    const char* bBase[4];
    int bOh[4], bOw[4];
    #pragma unroll
    for (int i = 0; i < 4; ++i) {
        const int row = rowA + 16 * i;       // 0..63
        bDst[i] = (uint32_t)(row * PITCH + segA * 16);
        const int pg = pix0 + row;
        const int n  = pg / HWI;
        const int hw = pg - n * HWI;
        bOh[i] = hw / 56;
        bOw[i] = hw - bOh[i] * 56;
        bBase[i] = (const char*)g_xh + ((size_t)n * HWI * C_IN + segA * 8) * 2;
    }

    // ---- ldmatrix lane addressing ----
    const uint32_t aOffB = (uint32_t)((wm * 64 + (lane & 15)) * PITCH + (lane >> 4) * 16);
    const int bRow = ((lane >> 4) << 3) | (lane & 7);
    const int bSel = (lane >> 3) & 1;
    const uint32_t bOffB = (uint32_t)((wn * 32 + bRow) * PITCH + bSel * 16);

    float acc[4][4][4];
    #pragma unroll
    for (int i = 0; i < 4; i++)
        #pragma unroll
        for (int j = 0; j < 4; j++)
            #pragma unroll
            for (int q = 0; q < 4; q++)
                acc[i][j][q] = 0.0f;

    // ---- fill one stage with chunk ck (BK=64 = half tap) ----
    auto fill_stage = [&](int ck, uint32_t st) {
        const int tp  = ck >> 1;
        const int fr  = (tp * 11) >> 5;           // tp/3 for tp<9
        const int fs  = tp - fr * 3;
        const int fc0 = (ck & 1) * 64;
        const uint64_t kB = (uint64_t)ck * BK * 2;
        #pragma unroll
        for (int i = 0; i < 8; ++i)
            cp16(st + OFF_A + aDst0 + (uint32_t)(i * 16 * PITCH),
                 aSrc0 + kB + (size_t)i * 16 * KDIM * 2);
        #pragma unroll
        for (int i = 0; i < 4; ++i) {
            const int ih = bOh[i] + fr - 1;
            const int iw = bOw[i] + fs - 1;
            const uint32_t ok = ((unsigned)ih < 56u && (unsigned)iw < 56u) ? 16u : 0u;
            const char* src = bBase[i] + ((ptrdiff_t)(ih * 56 + iw) * C_IN + fc0) * 2;
            cp16z(st + OFF_B + bDst[i], src, ok);
        }
        asm volatile("cp.async.commit_group;" ::: "memory");
    };

    // ---- prologue: fill stage 0 with chunk 0 ----
    fill_stage(0, sb);

    #pragma unroll 1
    for (int chunk = 0; chunk < NCHUNK; ++chunk) {
        asm volatile("cp.async.wait_group 0;" ::: "memory");
        __syncthreads();

        // ---- issue chunk+1 into the other stage (freed by the barrier) ----
        if (chunk + 1 < NCHUNK)
            fill_stage(chunk + 1, sb + (uint32_t)(((chunk + 1) & 1) * STAGE_B));

        // ---- MMA from stage chunk%2: 4 k16 steps x (4M x 4N tiles) ----
        const uint32_t bufS = sb + (uint32_t)((chunk & 1) * STAGE_B);
        #pragma unroll
        for (int ks = 0; ks < 4; ++ks) {
            const uint32_t ko = (uint32_t)(ks * 32);
            uint32_t bf[8];
            #pragma unroll
            for (int nb = 0; nb < 2; ++nb)
                ldsm4(&bf[nb * 4], bufS + OFF_B + bOffB + ko + (uint32_t)(nb * 16 * PITCH));
            uint32_t af[16];
            #pragma unroll
            for (int mt = 0; mt < 4; ++mt)
                ldsm4(&af[mt * 4], bufS + OFF_A + aOffB + ko + (uint32_t)(mt * 16 * PITCH));
            #pragma unroll
            for (int mt = 0; mt < 4; ++mt)
                #pragma unroll
                for (int nt = 0; nt < 4; ++nt)
                    mma16816(acc[mt][nt], &af[mt * 4], bf[nt * 2], bf[nt * 2 + 1]);
        }
    }

    // ---- epilogue ----
    #pragma unroll
    for (int mt = 0; mt < 4; ++mt) {
        const int r0 = oc0 + wm * 64 + mt * 16 + (lane >> 2);
        const int r1 = r0 + 8;
        const float bv0 = __ldg(&bias[r0]);
        const float bv1 = __ldg(&bias[r1]);
        #pragma unroll
        for (int nt = 0; nt < 4; ++nt) {
            const int pg   = pix0 + wn * 32 + nt * 8 + (lane & 3) * 2;
            const int nimg = pg / HWI;
            const int hw   = pg - nimg * HWI;
            const float* c = acc[mt][nt];
            float2 v0 = make_float2(c[0] + bv0, c[1] + bv0);
            float2 v1 = make_float2(c[2] + bv1, c[3] + bv1);
            *(float2*)&out[((size_t)nimg * 256 + r0) * HWI + hw] = v0;
            *(float2*)&out[((size_t)nimg * 256 + r1) * HWI + hw] = v1;
        }
    }
}

extern "C" void kernel_launch(void* const* d_in, const int* in_sizes, int n_in,
                              void* d_out, int out_size)
{
    const float* x    = (const float*)d_in[0];   // [32,128,56,56]
    const float* wgt  = (const float*)d_in[1];   // [256,128,3,3]
    const float* bias = (const float*)d_in[2];   // [256]
    float* out        = (float*)d_out;           // [32,256,56,56]

    cudaFuncSetAttribute(conv_main,
                         cudaFuncAttributeMaxDynamicSharedMemorySize, SMEM_TOTAL);

    prep_w<<<144, 256>>>(wgt);
    prep_nhwc<<<dim3(HWI / 64, 32), 256>>>(x);
    dim3 grid(2, NPIX / 64);                     // oc fast -> L2 reuse of B
    conv_main<<<grid, 128, SMEM_TOTAL>>>(bias, out);
}